// round 10
// baseline (speedup 1.0000x reference)
#include <cuda_runtime.h>
#include <cuda_fp16.h>
#include <mma.h>
#include <math.h>

using namespace nvcuda;

#define NN 100000
#define EE 1600000
#define EPAD (EE + 8 * NN)
#define HID 64
#define KORD 14
#define HEADS 8
#define NGRAPH 128
#define NCLS 10

// ---------------- scratch (device globals; no runtime alloc) ----------------
__device__ __half g_xh  [NN * 128];
__device__ __half g_yh  [NN * HID];
__device__ __half g_t1h [NN * HID];
__device__ __half g_t2h [NN * HID];
__device__ __half g_hh  [NN * HID];
__device__ int    g_deg[NN];
__device__ float  g_dinv[NN];
__device__ int    g_rowptr[NN + 1];   // padded prefix (multiples of 8)
__device__ int    g_cursor[NN];
__device__ int2   g_edge[EPAD];       // {col, float_bits(weight)}, zero-weight padding
__device__ float  g_coeff[3][KORD];
__device__ unsigned g_bar_count = 0;
__device__ unsigned g_bar_epoch = 0;

// ---------------- init ----------------
__global__ void init_kernel() {
    int i = blockIdx.x * blockDim.x + threadIdx.x;
    if (i < NN) g_deg[i] = 0;
}

__global__ void count_deg_kernel(const int* __restrict__ row) {
    int e = (blockIdx.x * blockDim.x + threadIdx.x) * 4;
    if (e < EE) {
        int4 r = *(const int4*)(row + e);
        atomicAdd(&g_deg[r.x], 1);
        atomicAdd(&g_deg[r.y], 1);
        atomicAdd(&g_deg[r.z], 1);
        atomicAdd(&g_deg[r.w], 1);
    }
}

// scan (padded degrees) + dinv + coeff fused; cursor seeded with rowptr
__global__ void scan_kernel(const float* __restrict__ theta1,
                            const float* __restrict__ thetas) {
    __shared__ int sums[1024];
    const int T = 1024;
    int tid = threadIdx.x;

    if (tid < 3 * KORD) {
        int layer = tid / KORD, k = tid % KORD;
        const float* th = (layer == 0) ? theta1 : thetas + (layer - 1) * HEADS * KORD;
        float s = 0.f;
        for (int h = 0; h < HEADS; h++) s += th[h * KORD + k];
        g_coeff[layer][k] = s * (1.0f / HEADS);
    }

    int per = (NN + T - 1) / T;
    int start = tid * per;
    int end = start + per; if (end > NN) end = NN;
    int local = 0;
    for (int i = start; i < end; i++) local += (g_deg[i] + 7) & ~7;
    sums[tid] = local;
    __syncthreads();
    for (int off = 1; off < T; off <<= 1) {
        int t = (tid >= off) ? sums[tid - off] : 0;
        __syncthreads();
        sums[tid] += t;
        __syncthreads();
    }
    int excl = sums[tid] - local;
    int run = excl;
    for (int i = start; i < end; i++) {
        int d = g_deg[i];
        g_rowptr[i] = run;
        g_cursor[i] = run;            // cursor starts at rowptr -> scatter does 1 atomic
        run += (d + 7) & ~7;
        g_dinv[i] = rsqrtf(fmaxf((float)d, 1.0f));
    }
    if (tid == T - 1) g_rowptr[NN] = run;
}

__global__ void scatter_kernel(const int* __restrict__ row, const int* __restrict__ col) {
    int e = (blockIdx.x * blockDim.x + threadIdx.x) * 2;
    if (e < EE) {
        int2 rr = *(const int2*)(row + e);
        int2 cc = *(const int2*)(col + e);
        int pos0 = atomicAdd(&g_cursor[rr.x], 1);
        g_edge[pos0] = make_int2(cc.x, __float_as_int(-g_dinv[rr.x] * g_dinv[cc.x]));
        int pos1 = atomicAdd(&g_cursor[rr.y], 1);
        g_edge[pos1] = make_int2(cc.y, __float_as_int(-g_dinv[rr.y] * g_dinv[cc.y]));
    }
}

__global__ void pad_fill_kernel() {
    int r = blockIdx.x * blockDim.x + threadIdx.x;
    if (r < NN) {
        int s = g_rowptr[r] + g_deg[r];
        int e = g_rowptr[r + 1];
        for (int i = s; i < e; i++) g_edge[i] = make_int2(0, 0);
    }
}

// ---------------- x -> fp16 ----------------
__global__ void convert_x_kernel(const float* __restrict__ x, __half* __restrict__ xh) {
    int i = (blockIdx.x * blockDim.x + threadIdx.x) * 4;
    if (i < NN * 128) {
        float4 v = *(const float4*)(x + i);
        __half2 h0 = __floats2half2_rn(v.x, v.y);
        __half2 h1 = __floats2half2_rn(v.z, v.w);
        int2 pk;
        pk.x = *(int*)&h0; pk.y = *(int*)&h1;
        *(int2*)(xh + i) = pk;
    }
}

// ---------------- wmma GEMM: Yh[N][64] = A[N][FIN] @ W[FIN][64] ----------------
template <int FIN>
__global__ __launch_bounds__(256) void gemm_wmma_kernel(const __half* __restrict__ A,
                                                        const float* __restrict__ W,
                                                        __half* __restrict__ Yh) {
    __shared__ __half As[128][40];
    __shared__ __half Ws[32][72];
    __shared__ float  Wb[8][16 * 20];
    int rowbase = blockIdx.x * 128;
    int tid = threadIdx.x;
    int wid = tid >> 5;
    int lane = tid & 31;

    wmma::fragment<wmma::accumulator, 16, 16, 16, float> acc[4];
#pragma unroll
    for (int i = 0; i < 4; i++) wmma::fill_fragment(acc[i], 0.f);

    for (int kk = 0; kk < FIN; kk += 32) {
#pragma unroll
        for (int i = 0; i < 4; i++) {
            int j = tid * 4 + i;
            int r = j >> 3;
            int kq = j & 7;
            int gr = rowbase + r;
            int2 v = make_int2(0, 0);
            if (gr < NN) v = *(const int2*)(A + (size_t)gr * FIN + kk + kq * 4);
            *(int2*)&As[r][kq * 4] = v;
        }
#pragma unroll
        for (int i = 0; i < 2; i++) {
            int j = tid * 2 + i;
            int k = j >> 4;
            int nq = j & 15;
            float4 v = *(const float4*)(W + (size_t)(kk + k) * 64 + nq * 4);
            __half2 h0 = __floats2half2_rn(v.x, v.y);
            __half2 h1 = __floats2half2_rn(v.z, v.w);
            int2 pk; pk.x = *(int*)&h0; pk.y = *(int*)&h1;
            *(int2*)&Ws[k][nq * 4] = pk;
        }
        __syncthreads();
#pragma unroll
        for (int ks = 0; ks < 32; ks += 16) {
            wmma::fragment<wmma::matrix_a, 16, 16, 16, __half, wmma::row_major> a_frag;
            wmma::load_matrix_sync(a_frag, &As[wid * 16][ks], 40);
#pragma unroll
            for (int nb = 0; nb < 4; nb++) {
                wmma::fragment<wmma::matrix_b, 16, 16, 16, __half, wmma::row_major> b_frag;
                wmma::load_matrix_sync(b_frag, &Ws[ks][nb * 16], 72);
                wmma::mma_sync(acc[nb], a_frag, b_frag, acc[nb]);
            }
        }
        __syncthreads();
    }
#pragma unroll
    for (int nb = 0; nb < 4; nb++) {
        wmma::store_matrix_sync(&Wb[wid][0], acc[nb], 20, wmma::mem_row_major);
        __syncwarp();
        int r = lane >> 1;
        int hc = lane & 1;
        int gr = rowbase + wid * 16 + r;
        if (gr < NN) {
            const float* src = &Wb[wid][r * 20 + hc * 8];
            __half2 o0 = __floats2half2_rn(src[0], src[1]);
            __half2 o1 = __floats2half2_rn(src[2], src[3]);
            __half2 o2 = __floats2half2_rn(src[4], src[5]);
            __half2 o3 = __floats2half2_rn(src[6], src[7]);
            int4 pk;
            pk.x = *(int*)&o0; pk.y = *(int*)&o1;
            pk.z = *(int*)&o2; pk.w = *(int*)&o3;
            *(int4*)(Yh + (size_t)gr * 64 + nb * 16 + hc * 8) = pk;
        }
        __syncwarp();
    }
}

// ---------------- prop + pack helpers ----------------
__device__ __forceinline__ void prop_row8(const int4* __restrict__ t,
                                          int st, int en, int sub, unsigned mask,
                                          float* __restrict__ acc) {
    const int4* tp = t + sub;
#pragma unroll
    for (int i = 0; i < 8; i++) acc[i] = 0.f;
    for (int base = st; base < en; base += 8) {
        int2 ew = __ldg(&g_edge[base + sub]);
        int4 raw[8];
#pragma unroll
        for (int j = 0; j < 8; j++) {
            int cj = __shfl_sync(mask, ew.x, j, 8);
            raw[j] = __ldg(&tp[(size_t)cj * 8]);
        }
#pragma unroll
        for (int j = 0; j < 8; j++) {
            float wj = __int_as_float(__shfl_sync(mask, ew.y, j, 8));
            const __half2* h = (const __half2*)&raw[j];
            float2 f0 = __half22float2(h[0]);
            float2 f1 = __half22float2(h[1]);
            float2 f2 = __half22float2(h[2]);
            float2 f3 = __half22float2(h[3]);
            acc[0] += wj * f0.x; acc[1] += wj * f0.y;
            acc[2] += wj * f1.x; acc[3] += wj * f1.y;
            acc[4] += wj * f2.x; acc[5] += wj * f2.y;
            acc[6] += wj * f3.x; acc[7] += wj * f3.y;
        }
    }
}

__device__ __forceinline__ int4 pack8(const float* v) {
    __half2 h0 = __floats2half2_rn(v[0], v[1]);
    __half2 h1 = __floats2half2_rn(v[2], v[3]);
    __half2 h2 = __floats2half2_rn(v[4], v[5]);
    __half2 h3 = __floats2half2_rn(v[6], v[7]);
    int4 r;
    r.x = *(int*)&h0; r.y = *(int*)&h1;
    r.z = *(int*)&h2; r.w = *(int*)&h3;
    return r;
}

__device__ __forceinline__ void unpack8(int4 raw, float* v) {
    const __half2* h = (const __half2*)&raw;
    float2 f0 = __half22float2(h[0]);
    float2 f1 = __half22float2(h[1]);
    float2 f2 = __half22float2(h[2]);
    float2 f3 = __half22float2(h[3]);
    v[0] = f0.x; v[1] = f0.y; v[2] = f1.x; v[3] = f1.y;
    v[4] = f2.x; v[5] = f2.y; v[6] = f3.x; v[7] = f3.y;
}

// ---------------- software grid barrier (all blocks co-resident) ----------------
__device__ __forceinline__ void grid_bar(int nblocks, unsigned target) {
    __syncthreads();
    if (threadIdx.x == 0) {
        __threadfence();
        unsigned old = atomicAdd(&g_bar_count, 1u);
        if (old == (unsigned)(nblocks - 1)) {
            g_bar_count = 0;
            __threadfence();
            atomicAdd(&g_bar_epoch, 1u);
        } else {
            while (atomicAdd(&g_bar_epoch, 0u) < target) __nanosleep(128);
        }
        __threadfence();
    }
    __syncthreads();
}

// ---------------- persistent per-layer Chebyshev kernel ----------------
// One launch runs all 13 prop steps. Each block owns rows [b*rpb, (b+1)*rpb),
// keeps the sum_k c_k T_k accumulator for those rows in fp16 smem.
// Global T buffers: 2-way ping-pong (blocks write only their own rows; the
// barrier separates each step's cross-block gathers from the next overwrite).
__global__ __launch_bounds__(512, 2) void cheb_layer_kernel(
        const __half* __restrict__ yh,
        __half* __restrict__ tA, __half* __restrict__ tB,
        const float* __restrict__ bias,
        __half* __restrict__ hout,
        int layer, int nblocks, int rpb) {
    extern __shared__ int4 s_out[];    // rpb*8 int4 = rpb rows x 64 fp16
    int tid = threadIdx.x;
    int lane = tid & 31;
    int sub = lane & 7;
    int group = tid >> 3;              // 0..63
    unsigned mask = 0xFFu << (lane & 24);
    int row0 = blockIdx.x * rpb;
    unsigned ebase = atomicAdd(&g_bar_epoch, 0u);
    unsigned bar = 0;

    float c0 = g_coeff[layer][0], c1 = g_coeff[layer][1];

    // ---- step 1: T1 = L~ y ; out = c0*y + c1*T1 ----
    for (int rr = group; rr < rpb; rr += 64) {
        int row = row0 + rr;
        if (row >= NN) break;
        float acc[8];
        prop_row8((const int4*)yh, g_rowptr[row], g_rowptr[row + 1], sub, mask, acc);
        size_t idx = (size_t)row * 8 + sub;
        float yv[8];
        unpack8(((const int4*)yh)[idx], yv);
        ((int4*)tA)[idx] = pack8(acc);
        float ov[8];
#pragma unroll
        for (int i = 0; i < 8; i++) ov[i] = c0 * yv[i] + c1 * acc[i];
        s_out[rr * 8 + sub] = pack8(ov);
    }
    grid_bar(nblocks, ebase + (++bar));

    // ---- steps k = 2..13 ----
    const __half* gat = tA;            // holds T_{k-1}
    const __half* pb  = yh;            // holds T_{k-2} (own rows)
    __half*       wb  = tB;            // write target for T_k
    for (int k = 2; k <= KORD - 1; k++) {
        float ck = g_coeff[layer][k];
        if (k < KORD - 1) {
            for (int rr = group; rr < rpb; rr += 64) {
                int row = row0 + rr;
                if (row >= NN) break;
                float acc[8];
                prop_row8((const int4*)gat, g_rowptr[row], g_rowptr[row + 1], sub, mask, acc);
                size_t idx = (size_t)row * 8 + sub;
                float p[8];
                unpack8(((const int4*)pb)[idx], p);
                float tn[8], o[8];
                unpack8(s_out[rr * 8 + sub], o);
#pragma unroll
                for (int i = 0; i < 8; i++) {
                    tn[i] = 2.f * acc[i] - p[i];
                    o[i] += ck * tn[i];
                }
                ((int4*)wb)[idx] = pack8(tn);
                s_out[rr * 8 + sub] = pack8(o);
            }
            grid_bar(nblocks, ebase + (++bar));
            const __half* old_gat = gat;
            gat = wb;
            pb  = old_gat;
            wb  = (__half*)old_gat;    // safe: own rows only, reads done pre-barrier
        } else {
            // last step: h = relu(out + ck * (2*prop - p) + bias)
            float4 b0 = *(const float4*)(bias + sub * 8);
            float4 b1 = *(const float4*)(bias + sub * 8 + 4);
            float bb[8] = {b0.x, b0.y, b0.z, b0.w, b1.x, b1.y, b1.z, b1.w};
            for (int rr = group; rr < rpb; rr += 64) {
                int row = row0 + rr;
                if (row >= NN) break;
                float acc[8];
                prop_row8((const int4*)gat, g_rowptr[row], g_rowptr[row + 1], sub, mask, acc);
                size_t idx = (size_t)row * 8 + sub;
                float p[8], o[8];
                unpack8(((const int4*)pb)[idx], p);
                unpack8(s_out[rr * 8 + sub], o);
                float r[8];
#pragma unroll
                for (int i = 0; i < 8; i++) {
                    float tni = 2.f * acc[i] - p[i];
                    r[i] = fmaxf(o[i] + ck * tni + bb[i], 0.f);
                }
                ((int4*)hout)[idx] = pack8(r);
            }
        }
    }
}

// ---------------- pool (fp16 input) + head + log_softmax ----------------
__global__ __launch_bounds__(256) void pool_head_kernel(const __half* __restrict__ h,
                                                        const int* __restrict__ batch,
                                                        const float* __restrict__ lin1w,
                                                        const float* __restrict__ lin1b,
                                                        const float* __restrict__ lin2w,
                                                        const float* __restrict__ lin2b,
                                                        float* __restrict__ out) {
    int g = blockIdx.x;
    int tid = threadIdx.x;
    int lo = 0, hi = NN;
    while (lo < hi) { int m = (lo + hi) >> 1; if (batch[m] < g) lo = m + 1; else hi = m; }
    int start = lo;
    lo = start; hi = NN;
    while (lo < hi) { int m = (lo + hi) >> 1; if (batch[m] < g + 1) lo = m + 1; else hi = m; }
    int end = lo;

    int f = tid & 63, sub = tid >> 6;
    float acc = 0.f;
    for (int i = start + sub; i < end; i += 4)
        acc += __half2float(h[(size_t)i * HID + f]);
    __shared__ float red[4][64];
    red[sub][f] = acc;
    __syncthreads();
    __shared__ float pooled[64];
    if (tid < 64) {
        float s = red[0][tid] + red[1][tid] + red[2][tid] + red[3][tid];
        float cnt = (float)(end - start);
        pooled[tid] = s / fmaxf(cnt, 1.0f);
    }
    __syncthreads();
    __shared__ float g1[64];
    if (tid < 64) {
        float a = lin1b[tid];
        for (int fk = 0; fk < 64; fk++) a += pooled[fk] * lin1w[fk * 64 + tid];
        g1[tid] = fmaxf(a, 0.f);
    }
    __syncthreads();
    __shared__ float logits[NCLS];
    if (tid < NCLS) {
        float a = lin2b[tid];
        for (int fk = 0; fk < 64; fk++) a += g1[fk] * lin2w[fk * NCLS + tid];
        logits[tid] = a;
    }
    __syncthreads();
    __shared__ float s_lse;
    if (tid == 0) {
        float mx = logits[0];
        for (int c = 1; c < NCLS; c++) mx = fmaxf(mx, logits[c]);
        float s = 0.f;
        for (int c = 0; c < NCLS; c++) s += expf(logits[c] - mx);
        s_lse = mx + logf(s);
    }
    __syncthreads();
    if (tid < NCLS) out[g * NCLS + tid] = logits[tid] - s_lse;
}

// ---------------- host orchestration ----------------
extern "C" void kernel_launch(void* const* d_in, const int* in_sizes, int n_in,
                              void* d_out, int out_size) {
    const float* x      = (const float*)d_in[0];
    const int*   ei     = (const int*)d_in[1];
    const int*   batch  = (const int*)d_in[2];
    const float* W1     = (const float*)d_in[3];
    const float* theta1 = (const float*)d_in[4];
    const float* b1     = (const float*)d_in[5];
    const float* Ws     = (const float*)d_in[6];
    const float* thetas = (const float*)d_in[7];
    const float* bs     = (const float*)d_in[8];
    const float* lin1w  = (const float*)d_in[9];
    const float* lin1b  = (const float*)d_in[10];
    const float* lin2w  = (const float*)d_in[11];
    const float* lin2b  = (const float*)d_in[12];
    float* out = (float*)d_out;

    const int* row = ei;
    const int* col = ei + EE;

    void* pv;
    __half *p_xh, *p_yh, *p_t1h, *p_t2h, *p_hh;
    cudaGetSymbolAddress(&pv, g_xh);   p_xh  = (__half*)pv;
    cudaGetSymbolAddress(&pv, g_yh);   p_yh  = (__half*)pv;
    cudaGetSymbolAddress(&pv, g_t1h);  p_t1h = (__half*)pv;
    cudaGetSymbolAddress(&pv, g_t2h);  p_t2h = (__half*)pv;
    cudaGetSymbolAddress(&pv, g_hh);   p_hh  = (__half*)pv;

    // persistent-grid sizing: 2 blocks/SM guaranteed by smem+launch_bounds
    int nsm = 0;
    cudaDeviceGetAttribute(&nsm, cudaDevAttrMultiProcessorCount, 0);
    if (nsm <= 0) nsm = 148;
    int nblocks = 2 * nsm;
    int rpb = (NN + nblocks - 1) / nblocks;
    size_t smem = (size_t)rpb * 8 * sizeof(int4);   // rpb rows x 64 fp16
    cudaFuncSetAttribute(cheb_layer_kernel,
                         cudaFuncAttributeMaxDynamicSharedMemorySize, 100 * 1024);

    // ---- padded CSR build + x conversion ----
    init_kernel<<<(NN + 255) / 256, 256>>>();
    count_deg_kernel<<<(EE / 4 + 255) / 256, 256>>>(row);
    scan_kernel<<<1, 1024>>>(theta1, thetas);
    scatter_kernel<<<(EE / 2 + 255) / 256, 256>>>(row, col);
    pad_fill_kernel<<<(NN + 255) / 256, 256>>>();
    convert_x_kernel<<<(NN * 128 / 4 + 255) / 256, 256>>>(x, p_xh);

    // ---- 3 spectral layers: GEMM + persistent Chebyshev ----
    const int GEMM_GRID = (NN + 127) / 128;

    gemm_wmma_kernel<128><<<GEMM_GRID, 256>>>(p_xh, W1, p_yh);
    cheb_layer_kernel<<<nblocks, 512, smem>>>(p_yh, p_t1h, p_t2h, b1, p_hh, 0, nblocks, rpb);

    gemm_wmma_kernel<64><<<GEMM_GRID, 256>>>(p_hh, Ws, p_yh);
    cheb_layer_kernel<<<nblocks, 512, smem>>>(p_yh, p_t1h, p_t2h, bs, p_hh, 1, nblocks, rpb);

    gemm_wmma_kernel<64><<<GEMM_GRID, 256>>>(p_hh, Ws + 64 * 64, p_yh);
    cheb_layer_kernel<<<nblocks, 512, smem>>>(p_yh, p_t1h, p_t2h, bs + HID, p_hh, 2, nblocks, rpb);

    // ---- pool + head ----
    pool_head_kernel<<<NGRAPH, 256>>>(p_hh, batch, lin1w, lin1b, lin2w, lin2b, out);
}

// round 11
// speedup vs baseline: 1.4777x; 1.4777x over previous
#include <cuda_runtime.h>
#include <cuda_fp16.h>
#include <mma.h>
#include <math.h>

using namespace nvcuda;

#define NN 100000
#define EE 1600000
#define STRIDE 96                      // fixed edge slots per row (max deg ~50 << 96)
#define HID 64
#define KORD 14
#define HEADS 8
#define NGRAPH 128
#define NCLS 10

// ---------------- scratch (device globals; no runtime alloc) ----------------
__device__ __half g_xh  [NN * 128];
__device__ __half g_yh  [NN * HID];
__device__ __half g_t1h [NN * HID];
__device__ __half g_t2h [NN * HID];
__device__ __half g_hh  [NN * HID];
__device__ int    g_deg[NN];
__device__ float  g_dinv[NN];
__device__ int    g_cursor[NN];        // scatter cursor; after pad_fill: padded row end
__device__ int2   g_edge[NN * STRIDE]; // {col, float_bits(weight)}, zero-weight padding
__device__ float  g_coeff[3][KORD];

// ---------------- init: deg=0, cursor=row base ----------------
__global__ void init_kernel() {
    int i = blockIdx.x * blockDim.x + threadIdx.x;
    if (i < NN) { g_deg[i] = 0; g_cursor[i] = i * STRIDE; }
}

__global__ void count_deg_kernel(const int* __restrict__ row) {
    int e = (blockIdx.x * blockDim.x + threadIdx.x) * 4;
    if (e < EE) {
        int4 r = *(const int4*)(row + e);
        atomicAdd(&g_deg[r.x], 1);
        atomicAdd(&g_deg[r.y], 1);
        atomicAdd(&g_deg[r.z], 1);
        atomicAdd(&g_deg[r.w], 1);
    }
}

// dinv + per-layer coeff (block 0)
__global__ void dinv_coeff_kernel(const float* __restrict__ theta1,
                                  const float* __restrict__ thetas) {
    int i = blockIdx.x * blockDim.x + threadIdx.x;
    if (i < NN) g_dinv[i] = rsqrtf(fmaxf((float)g_deg[i], 1.0f));
    if (blockIdx.x == 0 && threadIdx.x < 3 * KORD) {
        int layer = threadIdx.x / KORD, k = threadIdx.x % KORD;
        const float* th = (layer == 0) ? theta1 : thetas + (layer - 1) * HEADS * KORD;
        float s = 0.f;
        for (int h = 0; h < HEADS; h++) s += th[h * KORD + k];
        g_coeff[layer][k] = s * (1.0f / HEADS);
    }
}

__global__ void scatter_kernel(const int* __restrict__ row, const int* __restrict__ col) {
    int e = (blockIdx.x * blockDim.x + threadIdx.x) * 2;
    if (e < EE) {
        int2 rr = *(const int2*)(row + e);
        int2 cc = *(const int2*)(col + e);
        int pos0 = atomicAdd(&g_cursor[rr.x], 1);
        g_edge[pos0] = make_int2(cc.x, __float_as_int(-g_dinv[rr.x] * g_dinv[cc.x]));
        int pos1 = atomicAdd(&g_cursor[rr.y], 1);
        g_edge[pos1] = make_int2(cc.y, __float_as_int(-g_dinv[rr.y] * g_dinv[cc.y]));
    }
}

// pad to multiple of 8 with zero-weight edges; store padded end in cursor
__global__ void pad_fill_kernel() {
    int r = blockIdx.x * blockDim.x + threadIdx.x;
    if (r < NN) {
        int d = g_deg[r];
        int s = r * STRIDE + d;
        int e = r * STRIDE + ((d + 7) & ~7);
        for (int i = s; i < e; i++) g_edge[i] = make_int2(0, 0);
        g_cursor[r] = e;
    }
}

// ---------------- x -> fp16 ----------------
__global__ void convert_x_kernel(const float* __restrict__ x, __half* __restrict__ xh) {
    int i = (blockIdx.x * blockDim.x + threadIdx.x) * 4;
    if (i < NN * 128) {
        float4 v = *(const float4*)(x + i);
        __half2 h0 = __floats2half2_rn(v.x, v.y);
        __half2 h1 = __floats2half2_rn(v.z, v.w);
        int2 pk;
        pk.x = *(int*)&h0; pk.y = *(int*)&h1;
        *(int2*)(xh + i) = pk;
    }
}

// ---------------- wmma GEMM: Yh[N][64] = A[N][FIN] @ W[FIN][64] ----------------
template <int FIN>
__global__ __launch_bounds__(256) void gemm_wmma_kernel(const __half* __restrict__ A,
                                                        const float* __restrict__ W,
                                                        __half* __restrict__ Yh) {
    __shared__ __half As[128][40];
    __shared__ __half Ws[32][72];
    __shared__ float  Wb[8][16 * 20];
    int rowbase = blockIdx.x * 128;
    int tid = threadIdx.x;
    int wid = tid >> 5;
    int lane = tid & 31;

    wmma::fragment<wmma::accumulator, 16, 16, 16, float> acc[4];
#pragma unroll
    for (int i = 0; i < 4; i++) wmma::fill_fragment(acc[i], 0.f);

    for (int kk = 0; kk < FIN; kk += 32) {
#pragma unroll
        for (int i = 0; i < 4; i++) {
            int j = tid * 4 + i;
            int r = j >> 3;
            int kq = j & 7;
            int gr = rowbase + r;
            int2 v = make_int2(0, 0);
            if (gr < NN) v = *(const int2*)(A + (size_t)gr * FIN + kk + kq * 4);
            *(int2*)&As[r][kq * 4] = v;
        }
#pragma unroll
        for (int i = 0; i < 2; i++) {
            int j = tid * 2 + i;
            int k = j >> 4;
            int nq = j & 15;
            float4 v = *(const float4*)(W + (size_t)(kk + k) * 64 + nq * 4);
            __half2 h0 = __floats2half2_rn(v.x, v.y);
            __half2 h1 = __floats2half2_rn(v.z, v.w);
            int2 pk; pk.x = *(int*)&h0; pk.y = *(int*)&h1;
            *(int2*)&Ws[k][nq * 4] = pk;
        }
        __syncthreads();
#pragma unroll
        for (int ks = 0; ks < 32; ks += 16) {
            wmma::fragment<wmma::matrix_a, 16, 16, 16, __half, wmma::row_major> a_frag;
            wmma::load_matrix_sync(a_frag, &As[wid * 16][ks], 40);
#pragma unroll
            for (int nb = 0; nb < 4; nb++) {
                wmma::fragment<wmma::matrix_b, 16, 16, 16, __half, wmma::row_major> b_frag;
                wmma::load_matrix_sync(b_frag, &Ws[ks][nb * 16], 72);
                wmma::mma_sync(acc[nb], a_frag, b_frag, acc[nb]);
            }
        }
        __syncthreads();
    }
#pragma unroll
    for (int nb = 0; nb < 4; nb++) {
        wmma::store_matrix_sync(&Wb[wid][0], acc[nb], 20, wmma::mem_row_major);
        __syncwarp();
        int r = lane >> 1;
        int hc = lane & 1;
        int gr = rowbase + wid * 16 + r;
        if (gr < NN) {
            const float* src = &Wb[wid][r * 20 + hc * 8];
            __half2 o0 = __floats2half2_rn(src[0], src[1]);
            __half2 o1 = __floats2half2_rn(src[2], src[3]);
            __half2 o2 = __floats2half2_rn(src[4], src[5]);
            __half2 o3 = __floats2half2_rn(src[6], src[7]);
            int4 pk;
            pk.x = *(int*)&o0; pk.y = *(int*)&o1;
            pk.z = *(int*)&o2; pk.w = *(int*)&o3;
            *(int4*)(Yh + (size_t)gr * 64 + nb * 16 + hc * 8) = pk;
        }
        __syncwarp();
    }
}

// ---------------- Chebyshev propagation: 8-lane group per row, 8 features/lane ----------------
__device__ __forceinline__ void prop_row8(const int4* __restrict__ t,
                                          int st, int en, int sub, unsigned mask,
                                          float* __restrict__ acc) {
    const int4* tp = t + sub;
#pragma unroll
    for (int i = 0; i < 8; i++) acc[i] = 0.f;
    for (int base = st; base < en; base += 8) {
        int2 ew = __ldg(&g_edge[base + sub]);
        int4 raw[8];
#pragma unroll
        for (int j = 0; j < 8; j++) {
            int cj = __shfl_sync(mask, ew.x, j, 8);
            raw[j] = __ldg(&tp[(size_t)cj * 8]);
        }
#pragma unroll
        for (int j = 0; j < 8; j++) {
            float wj = __int_as_float(__shfl_sync(mask, ew.y, j, 8));
            const __half2* h = (const __half2*)&raw[j];
            float2 f0 = __half22float2(h[0]);
            float2 f1 = __half22float2(h[1]);
            float2 f2 = __half22float2(h[2]);
            float2 f3 = __half22float2(h[3]);
            acc[0] += wj * f0.x; acc[1] += wj * f0.y;
            acc[2] += wj * f1.x; acc[3] += wj * f1.y;
            acc[4] += wj * f2.x; acc[5] += wj * f2.y;
            acc[6] += wj * f3.x; acc[7] += wj * f3.y;
        }
    }
}

__device__ __forceinline__ int4 pack8(const float* v) {
    __half2 h0 = __floats2half2_rn(v[0], v[1]);
    __half2 h1 = __floats2half2_rn(v[2], v[3]);
    __half2 h2 = __floats2half2_rn(v[4], v[5]);
    __half2 h3 = __floats2half2_rn(v[6], v[7]);
    int4 r;
    r.x = *(int*)&h0; r.y = *(int*)&h1;
    r.z = *(int*)&h2; r.w = *(int*)&h3;
    return r;
}

__device__ __forceinline__ void unpack8(int4 raw, float* v) {
    const __half2* h = (const __half2*)&raw;
    float2 f0 = __half22float2(h[0]);
    float2 f1 = __half22float2(h[1]);
    float2 f2 = __half22float2(h[2]);
    float2 f3 = __half22float2(h[3]);
    v[0] = f0.x; v[1] = f0.y; v[2] = f1.x; v[3] = f1.y;
    v[4] = f2.x; v[5] = f2.y; v[6] = f3.x; v[7] = f3.y;
}

// first: t_cur = L~ y ; out = c0*y + c1*t_cur
__global__ __launch_bounds__(256) void cheb_first_kernel(const __half* __restrict__ yh,
                                                         __half* __restrict__ tcur,
                                                         __half* __restrict__ outb,
                                                         int layer) {
    int lane = threadIdx.x & 31;
    int sub = lane & 7;
    int row = blockIdx.x * 32 + (threadIdx.x >> 3);
    if (row >= NN) return;
    unsigned mask = 0xFFu << (lane & 24);
    int s = row * STRIDE, e = g_cursor[row];
    float acc[8];
    prop_row8((const int4*)yh, s, e, sub, mask, acc);
    float c0 = g_coeff[layer][0], c1 = g_coeff[layer][1];
    size_t idx = (size_t)row * 8 + sub;
    float yv[8];
    unpack8(((const int4*)yh)[idx], yv);
    ((int4*)tcur)[idx] = pack8(acc);
    float ov[8];
#pragma unroll
    for (int i = 0; i < 8; i++) ov[i] = c0 * yv[i] + c1 * acc[i];
    ((int4*)outb)[idx] = pack8(ov);
}

// step k: t_next = 2*L~ t_cur - t_prev ; out += c_k * t_next
__global__ __launch_bounds__(256) void cheb_step_kernel(const __half* __restrict__ tcur,
                                                        const __half* __restrict__ tprev,
                                                        __half* __restrict__ tnext,
                                                        __half* __restrict__ outb,
                                                        int layer, int k) {
    int lane = threadIdx.x & 31;
    int sub = lane & 7;
    int row = blockIdx.x * 32 + (threadIdx.x >> 3);
    if (row >= NN) return;
    unsigned mask = 0xFFu << (lane & 24);
    int s = row * STRIDE, e = g_cursor[row];
    float acc[8];
    prop_row8((const int4*)tcur, s, e, sub, mask, acc);
    size_t idx = (size_t)row * 8 + sub;
    float p[8], tn[8], o[8];
    unpack8(((const int4*)tprev)[idx], p);
#pragma unroll
    for (int i = 0; i < 8; i++) tn[i] = 2.f * acc[i] - p[i];
    ((int4*)tnext)[idx] = pack8(tn);
    float ck = g_coeff[layer][k];
    unpack8(((int4*)outb)[idx], o);
#pragma unroll
    for (int i = 0; i < 8; i++) o[i] += ck * tn[i];
    ((int4*)outb)[idx] = pack8(o);
}

// last step: h_out = relu(out + c_k*(2*L~ t_cur - t_prev) + bias)  (fp16 output)
__global__ __launch_bounds__(256) void cheb_last_kernel(const __half* __restrict__ tcur,
                                                        const __half* __restrict__ tprev,
                                                        const __half* __restrict__ outb,
                                                        const float* __restrict__ bias,
                                                        __half* __restrict__ hout,
                                                        int layer, int k) {
    int lane = threadIdx.x & 31;
    int sub = lane & 7;
    int row = blockIdx.x * 32 + (threadIdx.x >> 3);
    if (row >= NN) return;
    unsigned mask = 0xFFu << (lane & 24);
    int s = row * STRIDE, e = g_cursor[row];
    float acc[8];
    prop_row8((const int4*)tcur, s, e, sub, mask, acc);
    size_t idx = (size_t)row * 8 + sub;
    float p[8], o[8];
    unpack8(((const int4*)tprev)[idx], p);
    unpack8(((const int4*)outb)[idx], o);
    float ck = g_coeff[layer][k];
    float4 b0 = *(const float4*)(bias + sub * 8);
    float4 b1 = *(const float4*)(bias + sub * 8 + 4);
    float bb[8] = {b0.x, b0.y, b0.z, b0.w, b1.x, b1.y, b1.z, b1.w};
    float r[8];
#pragma unroll
    for (int i = 0; i < 8; i++) {
        float tni = 2.f * acc[i] - p[i];
        r[i] = fmaxf(o[i] + ck * tni + bb[i], 0.f);
    }
    ((int4*)hout)[idx] = pack8(r);
}

// ---------------- pool (fp16 input) + head + log_softmax ----------------
__global__ __launch_bounds__(256) void pool_head_kernel(const __half* __restrict__ h,
                                                        const int* __restrict__ batch,
                                                        const float* __restrict__ lin1w,
                                                        const float* __restrict__ lin1b,
                                                        const float* __restrict__ lin2w,
                                                        const float* __restrict__ lin2b,
                                                        float* __restrict__ out) {
    int g = blockIdx.x;
    int tid = threadIdx.x;
    int lo = 0, hi = NN;
    while (lo < hi) { int m = (lo + hi) >> 1; if (batch[m] < g) lo = m + 1; else hi = m; }
    int start = lo;
    lo = start; hi = NN;
    while (lo < hi) { int m = (lo + hi) >> 1; if (batch[m] < g + 1) lo = m + 1; else hi = m; }
    int end = lo;

    int f = tid & 63, sub = tid >> 6;
    float acc = 0.f;
    for (int i = start + sub; i < end; i += 4)
        acc += __half2float(h[(size_t)i * HID + f]);
    __shared__ float red[4][64];
    red[sub][f] = acc;
    __syncthreads();
    __shared__ float pooled[64];
    if (tid < 64) {
        float s = red[0][tid] + red[1][tid] + red[2][tid] + red[3][tid];
        float cnt = (float)(end - start);
        pooled[tid] = s / fmaxf(cnt, 1.0f);
    }
    __syncthreads();
    __shared__ float g1[64];
    if (tid < 64) {
        float a = lin1b[tid];
        for (int fk = 0; fk < 64; fk++) a += pooled[fk] * lin1w[fk * 64 + tid];
        g1[tid] = fmaxf(a, 0.f);
    }
    __syncthreads();
    __shared__ float logits[NCLS];
    if (tid < NCLS) {
        float a = lin2b[tid];
        for (int fk = 0; fk < 64; fk++) a += g1[fk] * lin2w[fk * NCLS + tid];
        logits[tid] = a;
    }
    __syncthreads();
    __shared__ float s_lse;
    if (tid == 0) {
        float mx = logits[0];
        for (int c = 1; c < NCLS; c++) mx = fmaxf(mx, logits[c]);
        float s = 0.f;
        for (int c = 0; c < NCLS; c++) s += expf(logits[c] - mx);
        s_lse = mx + logf(s);
    }
    __syncthreads();
    if (tid < NCLS) out[g * NCLS + tid] = logits[tid] - s_lse;
}

// ---------------- host orchestration ----------------
static void spectral_layer(const __half* hin, int fin, int layer,
                           const float* W, const float* bias,
                           __half* p_yh, __half* p_t1h, __half* p_t2h,
                           __half* p_outh, __half* hout) {
    const int CHEB_GRID = (NN + 31) / 32;
    const int GEMM_GRID = (NN + 127) / 128;
    if (fin == 128)
        gemm_wmma_kernel<128><<<GEMM_GRID, 256>>>(hin, W, p_yh);
    else
        gemm_wmma_kernel<64><<<GEMM_GRID, 256>>>(hin, W, p_yh);
    cheb_first_kernel<<<CHEB_GRID, 256>>>(p_yh, p_t1h, p_outh, layer);
    __half* tp = p_yh; __half* tc = p_t1h; __half* tn = p_t2h;
    for (int k = 2; k <= KORD - 2; k++) {
        cheb_step_kernel<<<CHEB_GRID, 256>>>(tc, tp, tn, p_outh, layer, k);
        __half* tmp = tp; tp = tc; tc = tn; tn = tmp;
    }
    cheb_last_kernel<<<CHEB_GRID, 256>>>(tc, tp, p_outh, bias, hout, layer, KORD - 1);
}

extern "C" void kernel_launch(void* const* d_in, const int* in_sizes, int n_in,
                              void* d_out, int out_size) {
    const float* x      = (const float*)d_in[0];
    const int*   ei     = (const int*)d_in[1];
    const int*   batch  = (const int*)d_in[2];
    const float* W1     = (const float*)d_in[3];
    const float* theta1 = (const float*)d_in[4];
    const float* b1     = (const float*)d_in[5];
    const float* Ws     = (const float*)d_in[6];
    const float* thetas = (const float*)d_in[7];
    const float* bs     = (const float*)d_in[8];
    const float* lin1w  = (const float*)d_in[9];
    const float* lin1b  = (const float*)d_in[10];
    const float* lin2w  = (const float*)d_in[11];
    const float* lin2b  = (const float*)d_in[12];
    float* out = (float*)d_out;

    const int* row = ei;
    const int* col = ei + EE;

    void* pv;
    __half *p_xh, *p_yh, *p_t1h, *p_t2h, *p_hh;
    __half* p_outh;
    cudaGetSymbolAddress(&pv, g_xh);   p_xh  = (__half*)pv;
    cudaGetSymbolAddress(&pv, g_yh);   p_yh  = (__half*)pv;
    cudaGetSymbolAddress(&pv, g_t1h);  p_t1h = (__half*)pv;
    cudaGetSymbolAddress(&pv, g_t2h);  p_t2h = (__half*)pv;
    cudaGetSymbolAddress(&pv, g_hh);   p_hh  = (__half*)pv;
    // out accumulator reuses the front half of g_xh after layer-0 GEMM? No —
    // g_xh is needed only for the first GEMM, but out is written during layer 0
    // props which happen after. Still, keep a dedicated region: reuse g_xh's
    // second half (NN*64 halves) as the out accumulator (g_xh is NN*128).
    p_outh = p_xh + (size_t)NN * 64;

    // ---- fixed-stride CSR build + x conversion ----
    init_kernel<<<(NN + 255) / 256, 256>>>();
    count_deg_kernel<<<(EE / 4 + 255) / 256, 256>>>(row);
    dinv_coeff_kernel<<<(NN + 255) / 256, 256>>>(theta1, thetas);
    scatter_kernel<<<(EE / 2 + 255) / 256, 256>>>(row, col);
    pad_fill_kernel<<<(NN + 255) / 256, 256>>>();
    convert_x_kernel<<<(NN * 128 / 4 + 255) / 256, 256>>>(x, p_xh);

    // ---- 3 spectral layers ----
    // NOTE: p_outh aliases g_xh[NN*64..NN*128) = x features 64..127. Layer 0's
    // GEMM reads all of g_xh BEFORE cheb_first writes p_outh (stream-ordered),
    // so this reuse is safe and deterministic.
    spectral_layer(p_xh, 128, 0, W1,           b1,       p_yh, p_t1h, p_t2h, p_outh, p_hh);
    spectral_layer(p_hh,  64, 1, Ws,           bs,       p_yh, p_t1h, p_t2h, p_outh, p_hh);
    spectral_layer(p_hh,  64, 2, Ws + 64 * 64, bs + HID, p_yh, p_t1h, p_t2h, p_outh, p_hh);

    // ---- pool + head ----
    pool_head_kernel<<<NGRAPH, 256>>>(p_hh, batch, lin1w, lin1b, lin2w, lin2b, out);
}

// round 12
// speedup vs baseline: 1.4981x; 1.0138x over previous
#include <cuda_runtime.h>
#include <cuda_fp16.h>
#include <mma.h>
#include <math.h>

using namespace nvcuda;

#define NN 100000
#define EE 1600000
#define STRIDE 96                      // fixed edge slots per row (max deg ~50 << 96)
#define HID 64
#define KORD 14
#define HEADS 8
#define NGRAPH 128
#define NCLS 10

// ---------------- scratch (device globals; no runtime alloc) ----------------
__device__ __half g_yh  [NN * HID];
__device__ __half g_t1h [NN * HID];
__device__ __half g_t2h [NN * HID];
__device__ __half g_outh[NN * HID];
__device__ __half g_hh  [NN * HID];
__device__ float  g_dinv[NN];
__device__ int    g_cursor[NN];        // scatter cursor; after weight_pad: padded row end
__device__ int    g_ecol[NN * STRIDE]; // column indices (+ zero padding)
__device__ __half g_ew  [NN * STRIDE]; // fp16 edge weights (+ zero padding)
__device__ float  g_coeff[3][KORD];

// ---------------- init: cursor = row base ----------------
__global__ void init_kernel() {
    int i = blockIdx.x * blockDim.x + threadIdx.x;
    if (i < NN) g_cursor[i] = i * STRIDE;
}

// one-pass scatter: columns only
__global__ void scatter_kernel(const int* __restrict__ row, const int* __restrict__ col) {
    int e = (blockIdx.x * blockDim.x + threadIdx.x) * 2;
    if (e < EE) {
        int2 rr = *(const int2*)(row + e);
        int2 cc = *(const int2*)(col + e);
        int pos0 = atomicAdd(&g_cursor[rr.x], 1);
        g_ecol[pos0] = cc.x;
        int pos1 = atomicAdd(&g_cursor[rr.y], 1);
        g_ecol[pos1] = cc.y;
    }
}

// dinv from cursor delta + per-layer coeff (block 0)
__global__ void dinv_coeff_kernel(const float* __restrict__ theta1,
                                  const float* __restrict__ thetas) {
    int i = blockIdx.x * blockDim.x + threadIdx.x;
    if (i < NN) {
        int d = g_cursor[i] - i * STRIDE;
        g_dinv[i] = rsqrtf(fmaxf((float)d, 1.0f));
    }
    if (blockIdx.x == 0 && threadIdx.x < 3 * KORD) {
        int layer = threadIdx.x / KORD, k = threadIdx.x % KORD;
        const float* th = (layer == 0) ? theta1 : thetas + (layer - 1) * HEADS * KORD;
        float s = 0.f;
        for (int h = 0; h < HEADS; h++) s += th[h * KORD + k];
        g_coeff[layer][k] = s * (1.0f / HEADS);
    }
}

// weights + padding; stores padded row end into cursor. 8 lanes per row.
__global__ void weight_pad_kernel() {
    int row = blockIdx.x * 32 + (threadIdx.x >> 3);
    int sub = threadIdx.x & 7;
    if (row >= NN) return;
    int base = row * STRIDE;
    int deg = g_cursor[row] - base;
    int pend = (deg + 7) & ~7;
    float dr = g_dinv[row];
    for (int i = sub; i < pend; i += 8) {
        int slot = base + i;
        if (i < deg) {
            int c = g_ecol[slot];
            g_ew[slot] = __float2half(-dr * g_dinv[c]);
        } else {
            g_ecol[slot] = 0;
            g_ew[slot] = __float2half(0.f);
        }
    }
    if (sub == 0) g_cursor[row] = base + pend;
}

// ---------------- wmma GEMM: Yh[N][64] = A[N][FIN] @ W[FIN][64] ----------------
template <int FIN, bool A_IS_FLOAT>
__global__ __launch_bounds__(256) void gemm_wmma_kernel(const void* __restrict__ Ain,
                                                        const float* __restrict__ W,
                                                        __half* __restrict__ Yh) {
    __shared__ __half As[128][40];
    __shared__ __half Ws[32][72];
    __shared__ float  Wb[8][16 * 20];
    int rowbase = blockIdx.x * 128;
    int tid = threadIdx.x;
    int wid = tid >> 5;
    int lane = tid & 31;

    wmma::fragment<wmma::accumulator, 16, 16, 16, float> acc[4];
#pragma unroll
    for (int i = 0; i < 4; i++) wmma::fill_fragment(acc[i], 0.f);

    for (int kk = 0; kk < FIN; kk += 32) {
        // stage A chunk: 128 rows x 32 values; 4 groups-of-4 per thread
#pragma unroll
        for (int i = 0; i < 4; i++) {
            int j = tid * 4 + i;          // 0..1023
            int r = j >> 3;               // 0..127
            int kq = j & 7;               // group of 4 values within row chunk
            int gr = rowbase + r;
            int2 pk = make_int2(0, 0);
            if (gr < NN) {
                if (A_IS_FLOAT) {
                    float4 v = *(const float4*)((const float*)Ain + (size_t)gr * FIN + kk + kq * 4);
                    __half2 h0 = __floats2half2_rn(v.x, v.y);
                    __half2 h1 = __floats2half2_rn(v.z, v.w);
                    pk.x = *(int*)&h0; pk.y = *(int*)&h1;
                } else {
                    pk = *(const int2*)((const __half*)Ain + (size_t)gr * FIN + kk + kq * 4);
                }
            }
            *(int2*)&As[r][kq * 4] = pk;
        }
        // stage W chunk: 32 k x 64 n fp32 -> fp16
#pragma unroll
        for (int i = 0; i < 2; i++) {
            int j = tid * 2 + i;
            int k = j >> 4;
            int nq = j & 15;
            float4 v = *(const float4*)(W + (size_t)(kk + k) * 64 + nq * 4);
            __half2 h0 = __floats2half2_rn(v.x, v.y);
            __half2 h1 = __floats2half2_rn(v.z, v.w);
            int2 pk; pk.x = *(int*)&h0; pk.y = *(int*)&h1;
            *(int2*)&Ws[k][nq * 4] = pk;
        }
        __syncthreads();
#pragma unroll
        for (int ks = 0; ks < 32; ks += 16) {
            wmma::fragment<wmma::matrix_a, 16, 16, 16, __half, wmma::row_major> a_frag;
            wmma::load_matrix_sync(a_frag, &As[wid * 16][ks], 40);
#pragma unroll
            for (int nb = 0; nb < 4; nb++) {
                wmma::fragment<wmma::matrix_b, 16, 16, 16, __half, wmma::row_major> b_frag;
                wmma::load_matrix_sync(b_frag, &Ws[ks][nb * 16], 72);
                wmma::mma_sync(acc[nb], a_frag, b_frag, acc[nb]);
            }
        }
        __syncthreads();
    }
#pragma unroll
    for (int nb = 0; nb < 4; nb++) {
        wmma::store_matrix_sync(&Wb[wid][0], acc[nb], 20, wmma::mem_row_major);
        __syncwarp();
        int r = lane >> 1;
        int hc = lane & 1;
        int gr = rowbase + wid * 16 + r;
        if (gr < NN) {
            const float* src = &Wb[wid][r * 20 + hc * 8];
            __half2 o0 = __floats2half2_rn(src[0], src[1]);
            __half2 o1 = __floats2half2_rn(src[2], src[3]);
            __half2 o2 = __floats2half2_rn(src[4], src[5]);
            __half2 o3 = __floats2half2_rn(src[6], src[7]);
            int4 pk;
            pk.x = *(int*)&o0; pk.y = *(int*)&o1;
            pk.z = *(int*)&o2; pk.w = *(int*)&o3;
            *(int4*)(Yh + (size_t)gr * 64 + nb * 16 + hc * 8) = pk;
        }
        __syncwarp();
    }
}

// ---------------- Chebyshev propagation: 8-lane group per row, 8 features/lane ----------------
__device__ __forceinline__ void prop_row8(const int4* __restrict__ t,
                                          int st, int en, int sub, unsigned mask,
                                          float* __restrict__ acc) {
    const int4* tp = t + sub;
#pragma unroll
    for (int i = 0; i < 8; i++) acc[i] = 0.f;
    for (int base = st; base < en; base += 8) {
        int c = __ldg(&g_ecol[base + sub]);
        float wf = __half2float(__ldg(&g_ew[base + sub]));
        int4 raw[8];
#pragma unroll
        for (int j = 0; j < 8; j++) {
            int cj = __shfl_sync(mask, c, j, 8);
            raw[j] = __ldg(&tp[(size_t)cj * 8]);
        }
#pragma unroll
        for (int j = 0; j < 8; j++) {
            float wj = __shfl_sync(mask, wf, j, 8);
            const __half2* h = (const __half2*)&raw[j];
            float2 f0 = __half22float2(h[0]);
            float2 f1 = __half22float2(h[1]);
            float2 f2 = __half22float2(h[2]);
            float2 f3 = __half22float2(h[3]);
            acc[0] += wj * f0.x; acc[1] += wj * f0.y;
            acc[2] += wj * f1.x; acc[3] += wj * f1.y;
            acc[4] += wj * f2.x; acc[5] += wj * f2.y;
            acc[6] += wj * f3.x; acc[7] += wj * f3.y;
        }
    }
}

__device__ __forceinline__ int4 pack8(const float* v) {
    __half2 h0 = __floats2half2_rn(v[0], v[1]);
    __half2 h1 = __floats2half2_rn(v[2], v[3]);
    __half2 h2 = __floats2half2_rn(v[4], v[5]);
    __half2 h3 = __floats2half2_rn(v[6], v[7]);
    int4 r;
    r.x = *(int*)&h0; r.y = *(int*)&h1;
    r.z = *(int*)&h2; r.w = *(int*)&h3;
    return r;
}

__device__ __forceinline__ void unpack8(int4 raw, float* v) {
    const __half2* h = (const __half2*)&raw;
    float2 f0 = __half22float2(h[0]);
    float2 f1 = __half22float2(h[1]);
    float2 f2 = __half22float2(h[2]);
    float2 f3 = __half22float2(h[3]);
    v[0] = f0.x; v[1] = f0.y; v[2] = f1.x; v[3] = f1.y;
    v[4] = f2.x; v[5] = f2.y; v[6] = f3.x; v[7] = f3.y;
}

// k=1: t_cur = L~ y  (no out activity)
__global__ __launch_bounds__(256) void cheb_first_kernel(const __half* __restrict__ yh,
                                                         __half* __restrict__ tcur) {
    int lane = threadIdx.x & 31;
    int sub = lane & 7;
    int row = blockIdx.x * 32 + (threadIdx.x >> 3);
    if (row >= NN) return;
    unsigned mask = 0xFFu << (lane & 24);
    int s = row * STRIDE, e = g_cursor[row];
    float acc[8];
    prop_row8((const int4*)yh, s, e, sub, mask, acc);
    ((int4*)tcur)[(size_t)row * 8 + sub] = pack8(acc);
}

// k>=2: t_next = 2*L~ t_cur - t_prev ; out handling per mode:
//   mode 0: none
//   mode 1 (k==2): out  = c0*p + c1*tcur[idx] + c2*tn   (write, no read)
//   mode 2 (even): out += c_{k-1}*tcur[idx] + c_k*tn
__global__ __launch_bounds__(256) void cheb_step_kernel(const __half* __restrict__ tcur,
                                                        const __half* __restrict__ tprev,
                                                        __half* __restrict__ tnext,
                                                        __half* __restrict__ outb,
                                                        int layer, int k, int mode) {
    int lane = threadIdx.x & 31;
    int sub = lane & 7;
    int row = blockIdx.x * 32 + (threadIdx.x >> 3);
    if (row >= NN) return;
    unsigned mask = 0xFFu << (lane & 24);
    int s = row * STRIDE, e = g_cursor[row];
    float acc[8];
    prop_row8((const int4*)tcur, s, e, sub, mask, acc);
    size_t idx = (size_t)row * 8 + sub;
    float p[8], tn[8];
    unpack8(((const int4*)tprev)[idx], p);
#pragma unroll
    for (int i = 0; i < 8; i++) tn[i] = 2.f * acc[i] - p[i];
    ((int4*)tnext)[idx] = pack8(tn);
    if (mode) {
        float ck = g_coeff[layer][k];
        float ckm = g_coeff[layer][k - 1];
        float tc[8], o[8];
        unpack8(((const int4*)tcur)[idx], tc);
        if (mode == 1) {
            float c0 = g_coeff[layer][0];
#pragma unroll
            for (int i = 0; i < 8; i++) o[i] = c0 * p[i] + ckm * tc[i] + ck * tn[i];
        } else {
            unpack8(((const int4*)outb)[idx], o);
#pragma unroll
            for (int i = 0; i < 8; i++) o[i] += ckm * tc[i] + ck * tn[i];
        }
        ((int4*)outb)[idx] = pack8(o);
    }
}

// k = KORD-1 (odd): h_out = relu(out + c_k*(2*L~ t_cur - t_prev) + bias)
__global__ __launch_bounds__(256) void cheb_last_kernel(const __half* __restrict__ tcur,
                                                        const __half* __restrict__ tprev,
                                                        const __half* __restrict__ outb,
                                                        const float* __restrict__ bias,
                                                        __half* __restrict__ hout,
                                                        int layer, int k) {
    int lane = threadIdx.x & 31;
    int sub = lane & 7;
    int row = blockIdx.x * 32 + (threadIdx.x >> 3);
    if (row >= NN) return;
    unsigned mask = 0xFFu << (lane & 24);
    int s = row * STRIDE, e = g_cursor[row];
    float acc[8];
    prop_row8((const int4*)tcur, s, e, sub, mask, acc);
    size_t idx = (size_t)row * 8 + sub;
    float p[8], o[8];
    unpack8(((const int4*)tprev)[idx], p);
    unpack8(((const int4*)outb)[idx], o);
    float ck = g_coeff[layer][k];
    float4 b0 = *(const float4*)(bias + sub * 8);
    float4 b1 = *(const float4*)(bias + sub * 8 + 4);
    float bb[8] = {b0.x, b0.y, b0.z, b0.w, b1.x, b1.y, b1.z, b1.w};
    float r[8];
#pragma unroll
    for (int i = 0; i < 8; i++) {
        float tni = 2.f * acc[i] - p[i];
        r[i] = fmaxf(o[i] + ck * tni + bb[i], 0.f);
    }
    ((int4*)hout)[idx] = pack8(r);
}

// ---------------- pool (fp16 input) + head + log_softmax ----------------
__global__ __launch_bounds__(256) void pool_head_kernel(const __half* __restrict__ h,
                                                        const int* __restrict__ batch,
                                                        const float* __restrict__ lin1w,
                                                        const float* __restrict__ lin1b,
                                                        const float* __restrict__ lin2w,
                                                        const float* __restrict__ lin2b,
                                                        float* __restrict__ out) {
    int g = blockIdx.x;
    int tid = threadIdx.x;
    int lo = 0, hi = NN;
    while (lo < hi) { int m = (lo + hi) >> 1; if (batch[m] < g) lo = m + 1; else hi = m; }
    int start = lo;
    lo = start; hi = NN;
    while (lo < hi) { int m = (lo + hi) >> 1; if (batch[m] < g + 1) lo = m + 1; else hi = m; }
    int end = lo;

    int f = tid & 63, sub = tid >> 6;
    float acc = 0.f;
    for (int i = start + sub; i < end; i += 4)
        acc += __half2float(h[(size_t)i * HID + f]);
    __shared__ float red[4][64];
    red[sub][f] = acc;
    __syncthreads();
    __shared__ float pooled[64];
    if (tid < 64) {
        float s = red[0][tid] + red[1][tid] + red[2][tid] + red[3][tid];
        float cnt = (float)(end - start);
        pooled[tid] = s / fmaxf(cnt, 1.0f);
    }
    __syncthreads();
    __shared__ float g1[64];
    if (tid < 64) {
        float a = lin1b[tid];
        for (int fk = 0; fk < 64; fk++) a += pooled[fk] * lin1w[fk * 64 + tid];
        g1[tid] = fmaxf(a, 0.f);
    }
    __syncthreads();
    __shared__ float logits[NCLS];
    if (tid < NCLS) {
        float a = lin2b[tid];
        for (int fk = 0; fk < 64; fk++) a += g1[fk] * lin2w[fk * NCLS + tid];
        logits[tid] = a;
    }
    __syncthreads();
    __shared__ float s_lse;
    if (tid == 0) {
        float mx = logits[0];
        for (int c = 1; c < NCLS; c++) mx = fmaxf(mx, logits[c]);
        float s = 0.f;
        for (int c = 0; c < NCLS; c++) s += expf(logits[c] - mx);
        s_lse = mx + logf(s);
    }
    __syncthreads();
    if (tid < NCLS) out[g * NCLS + tid] = logits[tid] - s_lse;
}

// ---------------- host orchestration ----------------
static void spectral_layer(const void* hin, int fin, int layer,
                           const float* W, const float* bias,
                           __half* p_yh, __half* p_t1h, __half* p_t2h,
                           __half* p_outh, __half* hout) {
    const int CHEB_GRID = (NN + 31) / 32;
    const int GEMM_GRID = (NN + 127) / 128;
    if (fin == 128)
        gemm_wmma_kernel<128, true><<<GEMM_GRID, 256>>>(hin, W, p_yh);
    else
        gemm_wmma_kernel<64, false><<<GEMM_GRID, 256>>>(hin, W, p_yh);
    cheb_first_kernel<<<CHEB_GRID, 256>>>(p_yh, p_t1h);
    __half* tp = p_yh; __half* tc = p_t1h; __half* tn = p_t2h;
    for (int k = 2; k <= KORD - 2; k++) {
        int mode = (k == 2) ? 1 : ((k & 1) ? 0 : 2);
        cheb_step_kernel<<<CHEB_GRID, 256>>>(tc, tp, tn, p_outh, layer, k, mode);
        __half* tmp = tp; tp = tc; tc = tn; tn = tmp;
    }
    cheb_last_kernel<<<CHEB_GRID, 256>>>(tc, tp, p_outh, bias, hout, layer, KORD - 1);
}

extern "C" void kernel_launch(void* const* d_in, const int* in_sizes, int n_in,
                              void* d_out, int out_size) {
    const float* x      = (const float*)d_in[0];
    const int*   ei     = (const int*)d_in[1];
    const int*   batch  = (const int*)d_in[2];
    const float* W1     = (const float*)d_in[3];
    const float* theta1 = (const float*)d_in[4];
    const float* b1     = (const float*)d_in[5];
    const float* Ws     = (const float*)d_in[6];
    const float* thetas = (const float*)d_in[7];
    const float* bs     = (const float*)d_in[8];
    const float* lin1w  = (const float*)d_in[9];
    const float* lin1b  = (const float*)d_in[10];
    const float* lin2w  = (const float*)d_in[11];
    const float* lin2b  = (const float*)d_in[12];
    float* out = (float*)d_out;

    const int* row = ei;
    const int* col = ei + EE;

    void* pv;
    __half *p_yh, *p_t1h, *p_t2h, *p_outh, *p_hh;
    cudaGetSymbolAddress(&pv, g_yh);   p_yh  = (__half*)pv;
    cudaGetSymbolAddress(&pv, g_t1h);  p_t1h = (__half*)pv;
    cudaGetSymbolAddress(&pv, g_t2h);  p_t2h = (__half*)pv;
    cudaGetSymbolAddress(&pv, g_outh); p_outh = (__half*)pv;
    cudaGetSymbolAddress(&pv, g_hh);   p_hh  = (__half*)pv;

    // ---- one-pass fixed-stride CSR build ----
    init_kernel<<<(NN + 255) / 256, 256>>>();
    scatter_kernel<<<(EE / 2 + 255) / 256, 256>>>(row, col);
    dinv_coeff_kernel<<<(NN + 255) / 256, 256>>>(theta1, thetas);
    weight_pad_kernel<<<(NN + 31) / 32, 256>>>();

    // ---- 3 spectral layers ----
    spectral_layer(x,    128, 0, W1,           b1,       p_yh, p_t1h, p_t2h, p_outh, p_hh);
    spectral_layer(p_hh,  64, 1, Ws,           bs,       p_yh, p_t1h, p_t2h, p_outh, p_hh);
    spectral_layer(p_hh,  64, 2, Ws + 64 * 64, bs + HID, p_yh, p_t1h, p_t2h, p_outh, p_hh);

    // ---- pool + head ----
    pool_head_kernel<<<NGRAPH, 256>>>(p_hh, batch, lin1w, lin1b, lin2w, lin2b, out);
}

// round 13
// speedup vs baseline: 1.5396x; 1.0277x over previous
#include <cuda_runtime.h>
#include <cuda_fp16.h>
#include <mma.h>
#include <math.h>

using namespace nvcuda;

#define NN 100000
#define EE 1600000
#define STRIDE 96                      // fixed edge slots per row (max deg ~50 << 96)
#define HID 64
#define KORD 14
#define HEADS 8
#define NGRAPH 128
#define NCLS 10

// ---------------- scratch (device globals; no runtime alloc) ----------------
// z-space Chebyshev buffers have an extra zero row (index NN) for padding edges.
__device__ __half g_yh  [(NN + 1) * HID];
__device__ __half g_t1h [(NN + 1) * HID];
__device__ __half g_t2h [(NN + 1) * HID];
__device__ __half g_outh[NN * HID];
__device__ __half g_hh  [NN * HID];
__device__ float  g_dinv[NN];          // dinv_i = rsqrt(max(deg,1))
__device__ float  g_m1d [NN];          // -dinv_i^2
__device__ float  g_rd  [NN];          // 1/dinv_i
__device__ int    g_cursor[NN];        // scatter cursor; after pad: padded row end
__device__ int    g_ecol[NN * STRIDE]; // column indices (padding -> NN)
__device__ float  g_coeff[3][KORD];

// ---------------- init: cursor = row base; zero dummy row of z buffers ----------------
__global__ void init_kernel() {
    int i = blockIdx.x * blockDim.x + threadIdx.x;
    if (i < NN) g_cursor[i] = i * STRIDE;
    if (i < 8 * 3) {
        int b = i >> 3, j = i & 7;
        __half* buf = (b == 0) ? g_yh : (b == 1) ? g_t1h : g_t2h;
        ((int4*)buf)[(size_t)NN * 8 + j] = make_int4(0, 0, 0, 0);
    }
}

// one-pass scatter: columns only
__global__ void scatter_kernel(const int* __restrict__ row, const int* __restrict__ col) {
    int e = (blockIdx.x * blockDim.x + threadIdx.x) * 2;
    if (e < EE) {
        int2 rr = *(const int2*)(row + e);
        int2 cc = *(const int2*)(col + e);
        int pos0 = atomicAdd(&g_cursor[rr.x], 1);
        g_ecol[pos0] = cc.x;
        int pos1 = atomicAdd(&g_cursor[rr.y], 1);
        g_ecol[pos1] = cc.y;
    }
}

// dinv/m1d/rd from cursor delta + per-layer coeff (block 0) + pad cols with NN
__global__ void dinv_coeff_pad_kernel(const float* __restrict__ theta1,
                                      const float* __restrict__ thetas) {
    int i = blockIdx.x * blockDim.x + threadIdx.x;
    if (i < NN) {
        int base = i * STRIDE;
        int deg = g_cursor[i] - base;
        float df = fmaxf((float)deg, 1.0f);
        float dv = rsqrtf(df);
        g_dinv[i] = dv;
        g_m1d[i] = -dv * dv;
        g_rd[i] = sqrtf(df);
        int pend = (deg + 7) & ~7;
        for (int j = deg; j < pend; j++) g_ecol[base + j] = NN;   // dummy zero row
        g_cursor[i] = base + pend;
    }
    if (blockIdx.x == 0 && threadIdx.x < 3 * KORD) {
        int layer = threadIdx.x / KORD, k = threadIdx.x % KORD;
        const float* th = (layer == 0) ? theta1 : thetas + (layer - 1) * HEADS * KORD;
        float s = 0.f;
        for (int h = 0; h < HEADS; h++) s += th[h * KORD + k];
        g_coeff[layer][k] = s * (1.0f / HEADS);
    }
}

// ---------------- wmma GEMM: Zh[N][64] = dinv * (A[N][FIN] @ W[FIN][64]) ----------------
template <int FIN, bool A_IS_FLOAT>
__global__ __launch_bounds__(256) void gemm_wmma_kernel(const void* __restrict__ Ain,
                                                        const float* __restrict__ W,
                                                        __half* __restrict__ Zh) {
    __shared__ __half As[128][40];
    __shared__ __half Ws[32][72];
    __shared__ float  Wb[8][16 * 20];
    int rowbase = blockIdx.x * 128;
    int tid = threadIdx.x;
    int wid = tid >> 5;
    int lane = tid & 31;

    wmma::fragment<wmma::accumulator, 16, 16, 16, float> acc[4];
#pragma unroll
    for (int i = 0; i < 4; i++) wmma::fill_fragment(acc[i], 0.f);

    for (int kk = 0; kk < FIN; kk += 32) {
#pragma unroll
        for (int i = 0; i < 4; i++) {
            int j = tid * 4 + i;
            int r = j >> 3;
            int kq = j & 7;
            int gr = rowbase + r;
            int2 pk = make_int2(0, 0);
            if (gr < NN) {
                if (A_IS_FLOAT) {
                    float4 v = *(const float4*)((const float*)Ain + (size_t)gr * FIN + kk + kq * 4);
                    __half2 h0 = __floats2half2_rn(v.x, v.y);
                    __half2 h1 = __floats2half2_rn(v.z, v.w);
                    pk.x = *(int*)&h0; pk.y = *(int*)&h1;
                } else {
                    pk = *(const int2*)((const __half*)Ain + (size_t)gr * FIN + kk + kq * 4);
                }
            }
            *(int2*)&As[r][kq * 4] = pk;
        }
#pragma unroll
        for (int i = 0; i < 2; i++) {
            int j = tid * 2 + i;
            int k = j >> 4;
            int nq = j & 15;
            float4 v = *(const float4*)(W + (size_t)(kk + k) * 64 + nq * 4);
            __half2 h0 = __floats2half2_rn(v.x, v.y);
            __half2 h1 = __floats2half2_rn(v.z, v.w);
            int2 pk; pk.x = *(int*)&h0; pk.y = *(int*)&h1;
            *(int2*)&Ws[k][nq * 4] = pk;
        }
        __syncthreads();
#pragma unroll
        for (int ks = 0; ks < 32; ks += 16) {
            wmma::fragment<wmma::matrix_a, 16, 16, 16, __half, wmma::row_major> a_frag;
            wmma::load_matrix_sync(a_frag, &As[wid * 16][ks], 40);
#pragma unroll
            for (int nb = 0; nb < 4; nb++) {
                wmma::fragment<wmma::matrix_b, 16, 16, 16, __half, wmma::row_major> b_frag;
                wmma::load_matrix_sync(b_frag, &Ws[ks][nb * 16], 72);
                wmma::mma_sync(acc[nb], a_frag, b_frag, acc[nb]);
            }
        }
        __syncthreads();
    }
    // epilogue: scale by dinv (y -> z space), pack fp16
#pragma unroll
    for (int nb = 0; nb < 4; nb++) {
        wmma::store_matrix_sync(&Wb[wid][0], acc[nb], 20, wmma::mem_row_major);
        __syncwarp();
        int r = lane >> 1;
        int hc = lane & 1;
        int gr = rowbase + wid * 16 + r;
        if (gr < NN) {
            float dv = g_dinv[gr];
            const float* src = &Wb[wid][r * 20 + hc * 8];
            __half2 o0 = __floats2half2_rn(dv * src[0], dv * src[1]);
            __half2 o1 = __floats2half2_rn(dv * src[2], dv * src[3]);
            __half2 o2 = __floats2half2_rn(dv * src[4], dv * src[5]);
            __half2 o3 = __floats2half2_rn(dv * src[6], dv * src[7]);
            int4 pk;
            pk.x = *(int*)&o0; pk.y = *(int*)&o1;
            pk.z = *(int*)&o2; pk.w = *(int*)&o3;
            *(int4*)(Zh + (size_t)gr * 64 + nb * 16 + hc * 8) = pk;
        }
        __syncwarp();
    }
}

// ---------------- unweighted neighbor sum: 8-lane group per row, 8 features/lane ----------------
__device__ __forceinline__ void sum_row8(const int4* __restrict__ t,
                                         int st, int en, int sub, unsigned mask,
                                         float* __restrict__ acc) {
    const int4* tp = t + sub;
#pragma unroll
    for (int i = 0; i < 8; i++) acc[i] = 0.f;
    for (int base = st; base < en; base += 8) {
        int c = __ldg(&g_ecol[base + sub]);
        int4 raw[8];
#pragma unroll
        for (int j = 0; j < 8; j++) {
            int cj = __shfl_sync(mask, c, j, 8);
            raw[j] = __ldg(&tp[(size_t)cj * 8]);
        }
#pragma unroll
        for (int j = 0; j < 8; j++) {
            const __half2* h = (const __half2*)&raw[j];
            float2 f0 = __half22float2(h[0]);
            float2 f1 = __half22float2(h[1]);
            float2 f2 = __half22float2(h[2]);
            float2 f3 = __half22float2(h[3]);
            acc[0] += f0.x; acc[1] += f0.y;
            acc[2] += f1.x; acc[3] += f1.y;
            acc[4] += f2.x; acc[5] += f2.y;
            acc[6] += f3.x; acc[7] += f3.y;
        }
    }
}

__device__ __forceinline__ int4 pack8(const float* v) {
    __half2 h0 = __floats2half2_rn(v[0], v[1]);
    __half2 h1 = __floats2half2_rn(v[2], v[3]);
    __half2 h2 = __floats2half2_rn(v[4], v[5]);
    __half2 h3 = __floats2half2_rn(v[6], v[7]);
    int4 r;
    r.x = *(int*)&h0; r.y = *(int*)&h1;
    r.z = *(int*)&h2; r.w = *(int*)&h3;
    return r;
}

__device__ __forceinline__ void unpack8(int4 raw, float* v) {
    const __half2* h = (const __half2*)&raw;
    float2 f0 = __half22float2(h[0]);
    float2 f1 = __half22float2(h[1]);
    float2 f2 = __half22float2(h[2]);
    float2 f3 = __half22float2(h[3]);
    v[0] = f0.x; v[1] = f0.y; v[2] = f1.x; v[3] = f1.y;
    v[4] = f2.x; v[5] = f2.y; v[6] = f3.x; v[7] = f3.y;
}

// k=1: z1 = m1d * sum(z0 over neighbors)
__global__ __launch_bounds__(256) void cheb_first_kernel(const __half* __restrict__ zy,
                                                         __half* __restrict__ zcur) {
    int lane = threadIdx.x & 31;
    int sub = lane & 7;
    int row = blockIdx.x * 32 + (threadIdx.x >> 3);
    if (row >= NN) return;
    unsigned mask = 0xFFu << (lane & 24);
    int s = row * STRIDE, e = g_cursor[row];
    float acc[8];
    sum_row8((const int4*)zy, s, e, sub, mask, acc);
    float m = g_m1d[row];
    float z1[8];
#pragma unroll
    for (int i = 0; i < 8; i++) z1[i] = m * acc[i];
    ((int4*)zcur)[(size_t)row * 8 + sub] = pack8(z1);
}

// k>=2: zn = 2*m1d*sum(zc) - zp ; out handling (z space):
//   mode 0: none
//   mode 1 (k==2): out  = c0*zp + c1*zc[idx] + c2*zn
//   mode 2 (even): out += c_{k-1}*zc[idx] + c_k*zn
__global__ __launch_bounds__(256) void cheb_step_kernel(const __half* __restrict__ zc,
                                                        const __half* __restrict__ zp,
                                                        __half* __restrict__ zn,
                                                        __half* __restrict__ outb,
                                                        int layer, int k, int mode) {
    int lane = threadIdx.x & 31;
    int sub = lane & 7;
    int row = blockIdx.x * 32 + (threadIdx.x >> 3);
    if (row >= NN) return;
    unsigned mask = 0xFFu << (lane & 24);
    int s = row * STRIDE, e = g_cursor[row];
    float acc[8];
    sum_row8((const int4*)zc, s, e, sub, mask, acc);
    size_t idx = (size_t)row * 8 + sub;
    float m2 = 2.f * g_m1d[row];
    float p[8], tn[8];
    unpack8(((const int4*)zp)[idx], p);
#pragma unroll
    for (int i = 0; i < 8; i++) tn[i] = m2 * acc[i] - p[i];
    ((int4*)zn)[idx] = pack8(tn);
    if (mode) {
        float ck = g_coeff[layer][k];
        float ckm = g_coeff[layer][k - 1];
        float tc[8], o[8];
        unpack8(((const int4*)zc)[idx], tc);
        if (mode == 1) {
            float c0 = g_coeff[layer][0];
#pragma unroll
            for (int i = 0; i < 8; i++) o[i] = c0 * p[i] + ckm * tc[i] + ck * tn[i];
        } else {
            unpack8(((const int4*)outb)[idx], o);
#pragma unroll
            for (int i = 0; i < 8; i++) o[i] += ckm * tc[i] + ck * tn[i];
        }
        ((int4*)outb)[idx] = pack8(o);
    }
}

// k = KORD-1 (odd): h = relu(rd*(out_z + c_k*zn) + bias)
__global__ __launch_bounds__(256) void cheb_last_kernel(const __half* __restrict__ zc,
                                                        const __half* __restrict__ zp,
                                                        const __half* __restrict__ outb,
                                                        const float* __restrict__ bias,
                                                        __half* __restrict__ hout,
                                                        int layer, int k) {
    int lane = threadIdx.x & 31;
    int sub = lane & 7;
    int row = blockIdx.x * 32 + (threadIdx.x >> 3);
    if (row >= NN) return;
    unsigned mask = 0xFFu << (lane & 24);
    int s = row * STRIDE, e = g_cursor[row];
    float acc[8];
    sum_row8((const int4*)zc, s, e, sub, mask, acc);
    size_t idx = (size_t)row * 8 + sub;
    float m2 = 2.f * g_m1d[row];
    float rd = g_rd[row];
    float p[8], o[8];
    unpack8(((const int4*)zp)[idx], p);
    unpack8(((const int4*)outb)[idx], o);
    float ck = g_coeff[layer][k];
    float4 b0 = *(const float4*)(bias + sub * 8);
    float4 b1 = *(const float4*)(bias + sub * 8 + 4);
    float bb[8] = {b0.x, b0.y, b0.z, b0.w, b1.x, b1.y, b1.z, b1.w};
    float r[8];
#pragma unroll
    for (int i = 0; i < 8; i++) {
        float tni = m2 * acc[i] - p[i];
        r[i] = fmaxf(rd * (o[i] + ck * tni) + bb[i], 0.f);
    }
    ((int4*)hout)[idx] = pack8(r);
}

// ---------------- pool (fp16 input) + head + log_softmax ----------------
__global__ __launch_bounds__(256) void pool_head_kernel(const __half* __restrict__ h,
                                                        const int* __restrict__ batch,
                                                        const float* __restrict__ lin1w,
                                                        const float* __restrict__ lin1b,
                                                        const float* __restrict__ lin2w,
                                                        const float* __restrict__ lin2b,
                                                        float* __restrict__ out) {
    int g = blockIdx.x;
    int tid = threadIdx.x;
    int lo = 0, hi = NN;
    while (lo < hi) { int m = (lo + hi) >> 1; if (batch[m] < g) lo = m + 1; else hi = m; }
    int start = lo;
    lo = start; hi = NN;
    while (lo < hi) { int m = (lo + hi) >> 1; if (batch[m] < g + 1) lo = m + 1; else hi = m; }
    int end = lo;

    int f = tid & 63, sub = tid >> 6;
    float acc = 0.f;
    for (int i = start + sub; i < end; i += 4)
        acc += __half2float(h[(size_t)i * HID + f]);
    __shared__ float red[4][64];
    red[sub][f] = acc;
    __syncthreads();
    __shared__ float pooled[64];
    if (tid < 64) {
        float s = red[0][tid] + red[1][tid] + red[2][tid] + red[3][tid];
        float cnt = (float)(end - start);
        pooled[tid] = s / fmaxf(cnt, 1.0f);
    }
    __syncthreads();
    __shared__ float g1[64];
    if (tid < 64) {
        float a = lin1b[tid];
        for (int fk = 0; fk < 64; fk++) a += pooled[fk] * lin1w[fk * 64 + tid];
        g1[tid] = fmaxf(a, 0.f);
    }
    __syncthreads();
    __shared__ float logits[NCLS];
    if (tid < NCLS) {
        float a = lin2b[tid];
        for (int fk = 0; fk < 64; fk++) a += g1[fk] * lin2w[fk * NCLS + tid];
        logits[tid] = a;
    }
    __syncthreads();
    __shared__ float s_lse;
    if (tid == 0) {
        float mx = logits[0];
        for (int c = 1; c < NCLS; c++) mx = fmaxf(mx, logits[c]);
        float s = 0.f;
        for (int c = 0; c < NCLS; c++) s += expf(logits[c] - mx);
        s_lse = mx + logf(s);
    }
    __syncthreads();
    if (tid < NCLS) out[g * NCLS + tid] = logits[tid] - s_lse;
}

// ---------------- host orchestration ----------------
static void spectral_layer(const void* hin, int fin, int layer,
                           const float* W, const float* bias,
                           __half* p_yh, __half* p_t1h, __half* p_t2h,
                           __half* p_outh, __half* hout) {
    const int CHEB_GRID = (NN + 31) / 32;
    const int GEMM_GRID = (NN + 127) / 128;
    if (fin == 128)
        gemm_wmma_kernel<128, true><<<GEMM_GRID, 256>>>(hin, W, p_yh);
    else
        gemm_wmma_kernel<64, false><<<GEMM_GRID, 256>>>(hin, W, p_yh);
    cheb_first_kernel<<<CHEB_GRID, 256>>>(p_yh, p_t1h);
    __half* tp = p_yh; __half* tc = p_t1h; __half* tn = p_t2h;
    for (int k = 2; k <= KORD - 2; k++) {
        int mode = (k == 2) ? 1 : ((k & 1) ? 0 : 2);
        cheb_step_kernel<<<CHEB_GRID, 256>>>(tc, tp, tn, p_outh, layer, k, mode);
        __half* tmp = tp; tp = tc; tc = tn; tn = tmp;
    }
    cheb_last_kernel<<<CHEB_GRID, 256>>>(tc, tp, p_outh, bias, hout, layer, KORD - 1);
}

extern "C" void kernel_launch(void* const* d_in, const int* in_sizes, int n_in,
                              void* d_out, int out_size) {
    const float* x      = (const float*)d_in[0];
    const int*   ei     = (const int*)d_in[1];
    const int*   batch  = (const int*)d_in[2];
    const float* W1     = (const float*)d_in[3];
    const float* theta1 = (const float*)d_in[4];
    const float* b1     = (const float*)d_in[5];
    const float* Ws     = (const float*)d_in[6];
    const float* thetas = (const float*)d_in[7];
    const float* bs     = (const float*)d_in[8];
    const float* lin1w  = (const float*)d_in[9];
    const float* lin1b  = (const float*)d_in[10];
    const float* lin2w  = (const float*)d_in[11];
    const float* lin2b  = (const float*)d_in[12];
    float* out = (float*)d_out;

    const int* row = ei;
    const int* col = ei + EE;

    void* pv;
    __half *p_yh, *p_t1h, *p_t2h, *p_outh, *p_hh;
    cudaGetSymbolAddress(&pv, g_yh);   p_yh  = (__half*)pv;
    cudaGetSymbolAddress(&pv, g_t1h);  p_t1h = (__half*)pv;
    cudaGetSymbolAddress(&pv, g_t2h);  p_t2h = (__half*)pv;
    cudaGetSymbolAddress(&pv, g_outh); p_outh = (__half*)pv;
    cudaGetSymbolAddress(&pv, g_hh);   p_hh  = (__half*)pv;

    // ---- one-pass fixed-stride CSR build (cols only) ----
    init_kernel<<<(NN + 255) / 256, 256>>>();
    scatter_kernel<<<(EE / 2 + 255) / 256, 256>>>(row, col);
    dinv_coeff_pad_kernel<<<(NN + 255) / 256, 256>>>(theta1, thetas);

    // ---- 3 spectral layers ----
    spectral_layer(x,    128, 0, W1,           b1,       p_yh, p_t1h, p_t2h, p_outh, p_hh);
    spectral_layer(p_hh,  64, 1, Ws,           bs,       p_yh, p_t1h, p_t2h, p_outh, p_hh);
    spectral_layer(p_hh,  64, 2, Ws + 64 * 64, bs + HID, p_yh, p_t1h, p_t2h, p_outh, p_hh);

    // ---- pool + head ----
    pool_head_kernel<<<NGRAPH, 256>>>(p_hh, batch, lin1w, lin1b, lin2w, lin2b, out);
}

// round 14
// speedup vs baseline: 1.7024x; 1.1057x over previous
#include <cuda_runtime.h>
#include <cuda_fp16.h>
#include <mma.h>
#include <math.h>

using namespace nvcuda;

#define NN 100000
#define EE 1600000
#define STRIDE 96                      // fixed edge slots per row (max deg ~50 << 96)
#define HID 64
#define KORD 14
#define HEADS 8
#define NGRAPH 128
#define NCLS 10

// ---------------- scratch (device globals; no runtime alloc) ----------------
// z-space Chebyshev buffers have an extra zero row (index NN) for padding edges.
__device__ __half g_yh  [(NN + 1) * HID];
__device__ __half g_t1h [(NN + 1) * HID];
__device__ __half g_t2h [(NN + 1) * HID];
__device__ __half g_outh[NN * HID];
__device__ __half g_hh  [NN * HID];
__device__ float  g_dinv[NN];          // dinv_i = rsqrt(max(deg,1))
__device__ float  g_m1d [NN];          // -dinv_i^2
__device__ float  g_rd  [NN];          // 1/dinv_i
__device__ int    g_cursor[NN];        // scatter cursor; after pad: padded row end
__device__ int    g_ecol[NN * STRIDE]; // column indices (padding -> NN)
__device__ float  g_coeff[3][KORD];

// ---------------- init: cursor = row base; zero dummy row of z buffers ----------------
__global__ void init_kernel() {
    int i = blockIdx.x * blockDim.x + threadIdx.x;
    if (i < NN) g_cursor[i] = i * STRIDE;
    if (i < 8 * 3) {
        int b = i >> 3, j = i & 7;
        __half* buf = (b == 0) ? g_yh : (b == 1) ? g_t1h : g_t2h;
        ((int4*)buf)[(size_t)NN * 8 + j] = make_int4(0, 0, 0, 0);
    }
}

// one-pass scatter: columns only
__global__ void scatter_kernel(const int* __restrict__ row, const int* __restrict__ col) {
    int e = (blockIdx.x * blockDim.x + threadIdx.x) * 2;
    if (e < EE) {
        int2 rr = *(const int2*)(row + e);
        int2 cc = *(const int2*)(col + e);
        int pos0 = atomicAdd(&g_cursor[rr.x], 1);
        g_ecol[pos0] = cc.x;
        int pos1 = atomicAdd(&g_cursor[rr.y], 1);
        g_ecol[pos1] = cc.y;
    }
}

// dinv/m1d/rd from cursor delta + per-layer coeff (block 0) + pad cols with NN
__global__ void dinv_coeff_pad_kernel(const float* __restrict__ theta1,
                                      const float* __restrict__ thetas) {
    int i = blockIdx.x * blockDim.x + threadIdx.x;
    if (i < NN) {
        int base = i * STRIDE;
        int deg = g_cursor[i] - base;
        float df = fmaxf((float)deg, 1.0f);
        float dv = rsqrtf(df);
        g_dinv[i] = dv;
        g_m1d[i] = -dv * dv;
        g_rd[i] = sqrtf(df);
        int pend = (deg + 7) & ~7;
        for (int j = deg; j < pend; j++) g_ecol[base + j] = NN;   // dummy zero row
        g_cursor[i] = base + pend;
    }
    if (blockIdx.x == 0 && threadIdx.x < 3 * KORD) {
        int layer = threadIdx.x / KORD, k = threadIdx.x % KORD;
        const float* th = (layer == 0) ? theta1 : thetas + (layer - 1) * HEADS * KORD;
        float s = 0.f;
        for (int h = 0; h < HEADS; h++) s += th[h * KORD + k];
        g_coeff[layer][k] = s * (1.0f / HEADS);
    }
}

// ---------------- wmma GEMM: Zh[N][64] = dinv * (A[N][FIN] @ W[FIN][64]) ----------------
template <int FIN, bool A_IS_FLOAT>
__global__ __launch_bounds__(256) void gemm_wmma_kernel(const void* __restrict__ Ain,
                                                        const float* __restrict__ W,
                                                        __half* __restrict__ Zh) {
    __shared__ __half As[128][40];
    __shared__ __half Ws[32][72];
    __shared__ float  Wb[8][16 * 20];
    int rowbase = blockIdx.x * 128;
    int tid = threadIdx.x;
    int wid = tid >> 5;
    int lane = tid & 31;

    wmma::fragment<wmma::accumulator, 16, 16, 16, float> acc[4];
#pragma unroll
    for (int i = 0; i < 4; i++) wmma::fill_fragment(acc[i], 0.f);

    for (int kk = 0; kk < FIN; kk += 32) {
#pragma unroll
        for (int i = 0; i < 4; i++) {
            int j = tid * 4 + i;
            int r = j >> 3;
            int kq = j & 7;
            int gr = rowbase + r;
            int2 pk = make_int2(0, 0);
            if (gr < NN) {
                if (A_IS_FLOAT) {
                    float4 v = *(const float4*)((const float*)Ain + (size_t)gr * FIN + kk + kq * 4);
                    __half2 h0 = __floats2half2_rn(v.x, v.y);
                    __half2 h1 = __floats2half2_rn(v.z, v.w);
                    pk.x = *(int*)&h0; pk.y = *(int*)&h1;
                } else {
                    pk = *(const int2*)((const __half*)Ain + (size_t)gr * FIN + kk + kq * 4);
                }
            }
            *(int2*)&As[r][kq * 4] = pk;
        }
#pragma unroll
        for (int i = 0; i < 2; i++) {
            int j = tid * 2 + i;
            int k = j >> 4;
            int nq = j & 15;
            float4 v = *(const float4*)(W + (size_t)(kk + k) * 64 + nq * 4);
            __half2 h0 = __floats2half2_rn(v.x, v.y);
            __half2 h1 = __floats2half2_rn(v.z, v.w);
            int2 pk; pk.x = *(int*)&h0; pk.y = *(int*)&h1;
            *(int2*)&Ws[k][nq * 4] = pk;
        }
        __syncthreads();
#pragma unroll
        for (int ks = 0; ks < 32; ks += 16) {
            wmma::fragment<wmma::matrix_a, 16, 16, 16, __half, wmma::row_major> a_frag;
            wmma::load_matrix_sync(a_frag, &As[wid * 16][ks], 40);
#pragma unroll
            for (int nb = 0; nb < 4; nb++) {
                wmma::fragment<wmma::matrix_b, 16, 16, 16, __half, wmma::row_major> b_frag;
                wmma::load_matrix_sync(b_frag, &Ws[ks][nb * 16], 72);
                wmma::mma_sync(acc[nb], a_frag, b_frag, acc[nb]);
            }
        }
        __syncthreads();
    }
    // epilogue: scale by dinv (y -> z space), pack fp16
#pragma unroll
    for (int nb = 0; nb < 4; nb++) {
        wmma::store_matrix_sync(&Wb[wid][0], acc[nb], 20, wmma::mem_row_major);
        __syncwarp();
        int r = lane >> 1;
        int hc = lane & 1;
        int gr = rowbase + wid * 16 + r;
        if (gr < NN) {
            float dv = g_dinv[gr];
            const float* src = &Wb[wid][r * 20 + hc * 8];
            __half2 o0 = __floats2half2_rn(dv * src[0], dv * src[1]);
            __half2 o1 = __floats2half2_rn(dv * src[2], dv * src[3]);
            __half2 o2 = __floats2half2_rn(dv * src[4], dv * src[5]);
            __half2 o3 = __floats2half2_rn(dv * src[6], dv * src[7]);
            int4 pk;
            pk.x = *(int*)&o0; pk.y = *(int*)&o1;
            pk.z = *(int*)&o2; pk.w = *(int*)&o3;
            *(int4*)(Zh + (size_t)gr * 64 + nb * 16 + hc * 8) = pk;
        }
        __syncwarp();
    }
}

// ---------------- unweighted neighbor sum: 8-lane group per row, 8 features/lane ----------------
// Broadcast col loads (no shuffles) + fp16 __hadd2 accumulation.
__device__ __forceinline__ void sum_row8(const int4* __restrict__ t,
                                         int st, int en, int sub,
                                         float* __restrict__ acc) {
    const int4* tp = t + sub;
    __half2 z = __float2half2_rn(0.f);
    __half2 a0 = z, a1 = z, a2 = z, a3 = z;
    for (int base = st; base < en; base += 8) {
        // all 8 lanes of the group load the same 32B of columns -> L1 broadcast
        int4 cA = __ldg((const int4*)&g_ecol[base]);
        int4 cB = __ldg((const int4*)&g_ecol[base + 4]);
        int4 raw[8];
        raw[0] = __ldg(&tp[(size_t)cA.x * 8]);
        raw[1] = __ldg(&tp[(size_t)cA.y * 8]);
        raw[2] = __ldg(&tp[(size_t)cA.z * 8]);
        raw[3] = __ldg(&tp[(size_t)cA.w * 8]);
        raw[4] = __ldg(&tp[(size_t)cB.x * 8]);
        raw[5] = __ldg(&tp[(size_t)cB.y * 8]);
        raw[6] = __ldg(&tp[(size_t)cB.z * 8]);
        raw[7] = __ldg(&tp[(size_t)cB.w * 8]);
#pragma unroll
        for (int j = 0; j < 8; j++) {
            const __half2* h = (const __half2*)&raw[j];
            a0 = __hadd2(a0, h[0]);
            a1 = __hadd2(a1, h[1]);
            a2 = __hadd2(a2, h[2]);
            a3 = __hadd2(a3, h[3]);
        }
    }
    float2 f0 = __half22float2(a0);
    float2 f1 = __half22float2(a1);
    float2 f2 = __half22float2(a2);
    float2 f3 = __half22float2(a3);
    acc[0] = f0.x; acc[1] = f0.y; acc[2] = f1.x; acc[3] = f1.y;
    acc[4] = f2.x; acc[5] = f2.y; acc[6] = f3.x; acc[7] = f3.y;
}

__device__ __forceinline__ int4 pack8(const float* v) {
    __half2 h0 = __floats2half2_rn(v[0], v[1]);
    __half2 h1 = __floats2half2_rn(v[2], v[3]);
    __half2 h2 = __floats2half2_rn(v[4], v[5]);
    __half2 h3 = __floats2half2_rn(v[6], v[7]);
    int4 r;
    r.x = *(int*)&h0; r.y = *(int*)&h1;
    r.z = *(int*)&h2; r.w = *(int*)&h3;
    return r;
}

__device__ __forceinline__ void unpack8(int4 raw, float* v) {
    const __half2* h = (const __half2*)&raw;
    float2 f0 = __half22float2(h[0]);
    float2 f1 = __half22float2(h[1]);
    float2 f2 = __half22float2(h[2]);
    float2 f3 = __half22float2(h[3]);
    v[0] = f0.x; v[1] = f0.y; v[2] = f1.x; v[3] = f1.y;
    v[4] = f2.x; v[5] = f2.y; v[6] = f3.x; v[7] = f3.y;
}

// k=1: z1 = m1d * sum(z0 over neighbors)
__global__ __launch_bounds__(256) void cheb_first_kernel(const __half* __restrict__ zy,
                                                         __half* __restrict__ zcur) {
    int sub = threadIdx.x & 7;
    int row = blockIdx.x * 32 + (threadIdx.x >> 3);
    if (row >= NN) return;
    int s = row * STRIDE, e = g_cursor[row];
    float acc[8];
    sum_row8((const int4*)zy, s, e, sub, acc);
    float m = g_m1d[row];
    float z1[8];
#pragma unroll
    for (int i = 0; i < 8; i++) z1[i] = m * acc[i];
    ((int4*)zcur)[(size_t)row * 8 + sub] = pack8(z1);
}

// k>=2: zn = 2*m1d*sum(zc) - zp ; out handling (z space):
//   mode 0: none
//   mode 1 (k==2): out  = c0*zp + c1*zc[idx] + c2*zn
//   mode 2 (even): out += c_{k-1}*zc[idx] + c_k*zn
__global__ __launch_bounds__(256) void cheb_step_kernel(const __half* __restrict__ zc,
                                                        const __half* __restrict__ zp,
                                                        __half* __restrict__ zn,
                                                        __half* __restrict__ outb,
                                                        int layer, int k, int mode) {
    int sub = threadIdx.x & 7;
    int row = blockIdx.x * 32 + (threadIdx.x >> 3);
    if (row >= NN) return;
    int s = row * STRIDE, e = g_cursor[row];
    float acc[8];
    sum_row8((const int4*)zc, s, e, sub, acc);
    size_t idx = (size_t)row * 8 + sub;
    float m2 = 2.f * g_m1d[row];
    float p[8], tn[8];
    unpack8(((const int4*)zp)[idx], p);
#pragma unroll
    for (int i = 0; i < 8; i++) tn[i] = m2 * acc[i] - p[i];
    ((int4*)zn)[idx] = pack8(tn);
    if (mode) {
        float ck = g_coeff[layer][k];
        float ckm = g_coeff[layer][k - 1];
        float tc[8], o[8];
        unpack8(((const int4*)zc)[idx], tc);
        if (mode == 1) {
            float c0 = g_coeff[layer][0];
#pragma unroll
            for (int i = 0; i < 8; i++) o[i] = c0 * p[i] + ckm * tc[i] + ck * tn[i];
        } else {
            unpack8(((const int4*)outb)[idx], o);
#pragma unroll
            for (int i = 0; i < 8; i++) o[i] += ckm * tc[i] + ck * tn[i];
        }
        ((int4*)outb)[idx] = pack8(o);
    }
}

// k = KORD-1 (odd): h = relu(rd*(out_z + c_k*zn) + bias)
__global__ __launch_bounds__(256) void cheb_last_kernel(const __half* __restrict__ zc,
                                                        const __half* __restrict__ zp,
                                                        const __half* __restrict__ outb,
                                                        const float* __restrict__ bias,
                                                        __half* __restrict__ hout,
                                                        int layer, int k) {
    int sub = threadIdx.x & 7;
    int row = blockIdx.x * 32 + (threadIdx.x >> 3);
    if (row >= NN) return;
    int s = row * STRIDE, e = g_cursor[row];
    float acc[8];
    sum_row8((const int4*)zc, s, e, sub, acc);
    size_t idx = (size_t)row * 8 + sub;
    float m2 = 2.f * g_m1d[row];
    float rd = g_rd[row];
    float p[8], o[8];
    unpack8(((const int4*)zp)[idx], p);
    unpack8(((const int4*)outb)[idx], o);
    float ck = g_coeff[layer][k];
    float4 b0 = *(const float4*)(bias + sub * 8);
    float4 b1 = *(const float4*)(bias + sub * 8 + 4);
    float bb[8] = {b0.x, b0.y, b0.z, b0.w, b1.x, b1.y, b1.z, b1.w};
    float r[8];
#pragma unroll
    for (int i = 0; i < 8; i++) {
        float tni = m2 * acc[i] - p[i];
        r[i] = fmaxf(rd * (o[i] + ck * tni) + bb[i], 0.f);
    }
    ((int4*)hout)[idx] = pack8(r);
}

// ---------------- pool (fp16 input) + head + log_softmax ----------------
__global__ __launch_bounds__(256) void pool_head_kernel(const __half* __restrict__ h,
                                                        const int* __restrict__ batch,
                                                        const float* __restrict__ lin1w,
                                                        const float* __restrict__ lin1b,
                                                        const float* __restrict__ lin2w,
                                                        const float* __restrict__ lin2b,
                                                        float* __restrict__ out) {
    int g = blockIdx.x;
    int tid = threadIdx.x;
    int lo = 0, hi = NN;
    while (lo < hi) { int m = (lo + hi) >> 1; if (batch[m] < g) lo = m + 1; else hi = m; }
    int start = lo;
    lo = start; hi = NN;
    while (lo < hi) { int m = (lo + hi) >> 1; if (batch[m] < g + 1) lo = m + 1; else hi = m; }
    int end = lo;

    int f = tid & 63, sub = tid >> 6;
    float acc = 0.f;
    for (int i = start + sub; i < end; i += 4)
        acc += __half2float(h[(size_t)i * HID + f]);
    __shared__ float red[4][64];
    red[sub][f] = acc;
    __syncthreads();
    __shared__ float pooled[64];
    if (tid < 64) {
        float s = red[0][tid] + red[1][tid] + red[2][tid] + red[3][tid];
        float cnt = (float)(end - start);
        pooled[tid] = s / fmaxf(cnt, 1.0f);
    }
    __syncthreads();
    __shared__ float g1[64];
    if (tid < 64) {
        float a = lin1b[tid];
        for (int fk = 0; fk < 64; fk++) a += pooled[fk] * lin1w[fk * 64 + tid];
        g1[tid] = fmaxf(a, 0.f);
    }
    __syncthreads();
    __shared__ float logits[NCLS];
    if (tid < NCLS) {
        float a = lin2b[tid];
        for (int fk = 0; fk < 64; fk++) a += g1[fk] * lin2w[fk * NCLS + tid];
        logits[tid] = a;
    }
    __syncthreads();
    __shared__ float s_lse;
    if (tid == 0) {
        float mx = logits[0];
        for (int c = 1; c < NCLS; c++) mx = fmaxf(mx, logits[c]);
        float s = 0.f;
        for (int c = 0; c < NCLS; c++) s += expf(logits[c] - mx);
        s_lse = mx + logf(s);
    }
    __syncthreads();
    if (tid < NCLS) out[g * NCLS + tid] = logits[tid] - s_lse;
}

// ---------------- host orchestration ----------------
static void spectral_layer(const void* hin, int fin, int layer,
                           const float* W, const float* bias,
                           __half* p_yh, __half* p_t1h, __half* p_t2h,
                           __half* p_outh, __half* hout) {
    const int CHEB_GRID = (NN + 31) / 32;
    const int GEMM_GRID = (NN + 127) / 128;
    if (fin == 128)
        gemm_wmma_kernel<128, true><<<GEMM_GRID, 256>>>(hin, W, p_yh);
    else
        gemm_wmma_kernel<64, false><<<GEMM_GRID, 256>>>(hin, W, p_yh);
    cheb_first_kernel<<<CHEB_GRID, 256>>>(p_yh, p_t1h);
    __half* tp = p_yh; __half* tc = p_t1h; __half* tn = p_t2h;
    for (int k = 2; k <= KORD - 2; k++) {
        int mode = (k == 2) ? 1 : ((k & 1) ? 0 : 2);
        cheb_step_kernel<<<CHEB_GRID, 256>>>(tc, tp, tn, p_outh, layer, k, mode);
        __half* tmp = tp; tp = tc; tc = tn; tn = tmp;
    }
    cheb_last_kernel<<<CHEB_GRID, 256>>>(tc, tp, p_outh, bias, hout, layer, KORD - 1);
}

extern "C" void kernel_launch(void* const* d_in, const int* in_sizes, int n_in,
                              void* d_out, int out_size) {
    const float* x      = (const float*)d_in[0];
    const int*   ei     = (const int*)d_in[1];
    const int*   batch  = (const int*)d_in[2];
    const float* W1     = (const float*)d_in[3];
    const float* theta1 = (const float*)d_in[4];
    const float* b1     = (const float*)d_in[5];
    const float* Ws     = (const float*)d_in[6];
    const float* thetas = (const float*)d_in[7];
    const float* bs     = (const float*)d_in[8];
    const float* lin1w  = (const float*)d_in[9];
    const float* lin1b  = (const float*)d_in[10];
    const float* lin2w  = (const float*)d_in[11];
    const float* lin2b  = (const float*)d_in[12];
    float* out = (float*)d_out;

    const int* row = ei;
    const int* col = ei + EE;

    void* pv;
    __half *p_yh, *p_t1h, *p_t2h, *p_outh, *p_hh;
    cudaGetSymbolAddress(&pv, g_yh);   p_yh  = (__half*)pv;
    cudaGetSymbolAddress(&pv, g_t1h);  p_t1h = (__half*)pv;
    cudaGetSymbolAddress(&pv, g_t2h);  p_t2h = (__half*)pv;
    cudaGetSymbolAddress(&pv, g_outh); p_outh = (__half*)pv;
    cudaGetSymbolAddress(&pv, g_hh);   p_hh  = (__half*)pv;

    // ---- one-pass fixed-stride CSR build (cols only) ----
    init_kernel<<<(NN + 255) / 256, 256>>>();
    scatter_kernel<<<(EE / 2 + 255) / 256, 256>>>(row, col);
    dinv_coeff_pad_kernel<<<(NN + 255) / 256, 256>>>(theta1, thetas);

    // ---- 3 spectral layers ----
    spectral_layer(x,    128, 0, W1,           b1,       p_yh, p_t1h, p_t2h, p_outh, p_hh);
    spectral_layer(p_hh,  64, 1, Ws,           bs,       p_yh, p_t1h, p_t2h, p_outh, p_hh);
    spectral_layer(p_hh,  64, 2, Ws + 64 * 64, bs + HID, p_yh, p_t1h, p_t2h, p_outh, p_hh);

    // ---- pool + head ----
    pool_head_kernel<<<NGRAPH, 256>>>(p_hh, batch, lin1w, lin1b, lin2w, lin2b, out);
}

// round 15
// speedup vs baseline: 1.7221x; 1.0116x over previous
#include <cuda_runtime.h>
#include <cuda_fp16.h>
#include <mma.h>
#include <math.h>

using namespace nvcuda;

#define NN 100000
#define EE 1600000
#define STRIDE 96                      // fixed edge slots per row (max deg ~50 << 96)
#define HID 64
#define KORD 14
#define HEADS 8
#define NGRAPH 128
#define NCLS 10

// ---------------- scratch (device globals; no runtime alloc) ----------------
// z-space Chebyshev buffers have an extra zero row (index NN) for padding edges.
__device__ __half g_yh  [(NN + 1) * HID];
__device__ __half g_t1h [(NN + 1) * HID];
__device__ __half g_t2h [(NN + 1) * HID];
__device__ __half g_outh[NN * HID];
__device__ __half g_hh  [NN * HID];
__device__ float  g_dinv[NN];          // dinv_i = rsqrt(max(deg,1))
__device__ float  g_m1d [NN];          // -dinv_i^2
__device__ float  g_rd  [NN];          // 1/dinv_i
__device__ int    g_cursor[NN];        // scatter cursor; after pad: padded row end
__device__ int    g_ecol[NN * STRIDE]; // column indices (padding -> NN)
__device__ float  g_coeff[3][KORD];

// ---------------- init: cursor = row base; zero dummy row of z buffers ----------------
__global__ void init_kernel() {
    int i = blockIdx.x * blockDim.x + threadIdx.x;
    if (i < NN) g_cursor[i] = i * STRIDE;
    if (i < 8 * 3) {
        int b = i >> 3, j = i & 7;
        __half* buf = (b == 0) ? g_yh : (b == 1) ? g_t1h : g_t2h;
        ((int4*)buf)[(size_t)NN * 8 + j] = make_int4(0, 0, 0, 0);
    }
}

// one-pass scatter: columns only, 4 edges per thread
__global__ void scatter_kernel(const int* __restrict__ row, const int* __restrict__ col) {
    int e = (blockIdx.x * blockDim.x + threadIdx.x) * 4;
    if (e < EE) {
        int4 rr = *(const int4*)(row + e);
        int4 cc = *(const int4*)(col + e);
        int pos;
        pos = atomicAdd(&g_cursor[rr.x], 1); g_ecol[pos] = cc.x;
        pos = atomicAdd(&g_cursor[rr.y], 1); g_ecol[pos] = cc.y;
        pos = atomicAdd(&g_cursor[rr.z], 1); g_ecol[pos] = cc.z;
        pos = atomicAdd(&g_cursor[rr.w], 1); g_ecol[pos] = cc.w;
    }
}

// dinv/m1d/rd from cursor delta + per-layer coeff (block 0) + pad cols with NN
__global__ void dinv_coeff_pad_kernel(const float* __restrict__ theta1,
                                      const float* __restrict__ thetas) {
    int i = blockIdx.x * blockDim.x + threadIdx.x;
    if (i < NN) {
        int base = i * STRIDE;
        int deg = g_cursor[i] - base;
        float df = fmaxf((float)deg, 1.0f);
        float dv = rsqrtf(df);
        g_dinv[i] = dv;
        g_m1d[i] = -dv * dv;
        g_rd[i] = sqrtf(df);
        int pend = (deg + 7) & ~7;
        for (int j = deg; j < pend; j++) g_ecol[base + j] = NN;   // dummy zero row
        g_cursor[i] = base + pend;
    }
    if (blockIdx.x == 0 && threadIdx.x < 3 * KORD) {
        int layer = threadIdx.x / KORD, k = threadIdx.x % KORD;
        const float* th = (layer == 0) ? theta1 : thetas + (layer - 1) * HEADS * KORD;
        float s = 0.f;
        for (int h = 0; h < HEADS; h++) s += th[h * KORD + k];
        g_coeff[layer][k] = s * (1.0f / HEADS);
    }
}

// ---------------- wmma GEMM: Zh[N][64] = dinv * (A[N][FIN] @ W[FIN][64]) ----------------
// Software-pipelined: next K-chunk prefetched into registers while current
// chunk is consumed from smem (overlaps DRAM latency with MMA).
template <int FIN, bool A_IS_FLOAT>
__global__ __launch_bounds__(256) void gemm_wmma_kernel(const void* __restrict__ Ain,
                                                        const float* __restrict__ W,
                                                        __half* __restrict__ Zh) {
    __shared__ __half As[128][40];
    __shared__ __half Ws[32][72];
    __shared__ float  Wb[8][16 * 20];
    constexpr int NCHUNK = FIN / 32;
    int rowbase = blockIdx.x * 128;
    int tid = threadIdx.x;
    int wid = tid >> 5;
    int lane = tid & 31;

    // per-thread staging coordinates
    int ar = (tid * 4) >> 3;            // A row for first of 4 int2 (tid*4+i: same >>3 group of 2 rows)
    // A: j = tid*4+i, r=j>>3, kq=j&7  (recomputed inline below)
    // W: j = tid*2+i, k=j>>4, nq=j&15
    (void)ar;

    wmma::fragment<wmma::accumulator, 16, 16, 16, float> acc[4];
#pragma unroll
    for (int i = 0; i < 4; i++) wmma::fill_fragment(acc[i], 0.f);

    int2  aPk[4];       // prefetched A (already fp16-packed)
    int2  wPk[2];       // prefetched W (fp16-packed)

    auto prefetch = [&](int kk) {
#pragma unroll
        for (int i = 0; i < 4; i++) {
            int j = tid * 4 + i;
            int r = j >> 3;
            int kq = j & 7;
            int gr = rowbase + r;
            int2 pk = make_int2(0, 0);
            if (gr < NN) {
                if (A_IS_FLOAT) {
                    float4 v = *(const float4*)((const float*)Ain + (size_t)gr * FIN + kk + kq * 4);
                    __half2 h0 = __floats2half2_rn(v.x, v.y);
                    __half2 h1 = __floats2half2_rn(v.z, v.w);
                    pk.x = *(int*)&h0; pk.y = *(int*)&h1;
                } else {
                    pk = *(const int2*)((const __half*)Ain + (size_t)gr * FIN + kk + kq * 4);
                }
            }
            aPk[i] = pk;
        }
#pragma unroll
        for (int i = 0; i < 2; i++) {
            int j = tid * 2 + i;
            int k = j >> 4;
            int nq = j & 15;
            float4 v = *(const float4*)(W + (size_t)(kk + k) * 64 + nq * 4);
            __half2 h0 = __floats2half2_rn(v.x, v.y);
            __half2 h1 = __floats2half2_rn(v.z, v.w);
            wPk[i].x = *(int*)&h0; wPk[i].y = *(int*)&h1;
        }
    };

    prefetch(0);
#pragma unroll
    for (int c = 0; c < NCHUNK; c++) {
        // commit prefetched chunk to smem
#pragma unroll
        for (int i = 0; i < 4; i++) {
            int j = tid * 4 + i;
            int r = j >> 3;
            int kq = j & 7;
            *(int2*)&As[r][kq * 4] = aPk[i];
        }
#pragma unroll
        for (int i = 0; i < 2; i++) {
            int j = tid * 2 + i;
            int k = j >> 4;
            int nq = j & 15;
            *(int2*)&Ws[k][nq * 4] = wPk[i];
        }
        __syncthreads();
        if (c + 1 < NCHUNK) prefetch((c + 1) * 32);
#pragma unroll
        for (int ks = 0; ks < 32; ks += 16) {
            wmma::fragment<wmma::matrix_a, 16, 16, 16, __half, wmma::row_major> a_frag;
            wmma::load_matrix_sync(a_frag, &As[wid * 16][ks], 40);
#pragma unroll
            for (int nb = 0; nb < 4; nb++) {
                wmma::fragment<wmma::matrix_b, 16, 16, 16, __half, wmma::row_major> b_frag;
                wmma::load_matrix_sync(b_frag, &Ws[ks][nb * 16], 72);
                wmma::mma_sync(acc[nb], a_frag, b_frag, acc[nb]);
            }
        }
        __syncthreads();
    }
    // epilogue: scale by dinv (y -> z space), pack fp16
#pragma unroll
    for (int nb = 0; nb < 4; nb++) {
        wmma::store_matrix_sync(&Wb[wid][0], acc[nb], 20, wmma::mem_row_major);
        __syncwarp();
        int r = lane >> 1;
        int hc = lane & 1;
        int gr = rowbase + wid * 16 + r;
        if (gr < NN) {
            float dv = g_dinv[gr];
            const float* src = &Wb[wid][r * 20 + hc * 8];
            __half2 o0 = __floats2half2_rn(dv * src[0], dv * src[1]);
            __half2 o1 = __floats2half2_rn(dv * src[2], dv * src[3]);
            __half2 o2 = __floats2half2_rn(dv * src[4], dv * src[5]);
            __half2 o3 = __floats2half2_rn(dv * src[6], dv * src[7]);
            int4 pk;
            pk.x = *(int*)&o0; pk.y = *(int*)&o1;
            pk.z = *(int*)&o2; pk.w = *(int*)&o3;
            *(int4*)(Zh + (size_t)gr * 64 + nb * 16 + hc * 8) = pk;
        }
        __syncwarp();
    }
}

// ---------------- unweighted neighbor sum: 8-lane group per row, 8 features/lane ----------------
// Broadcast col loads (no shuffles) + fp16 __hadd2 accumulation.
__device__ __forceinline__ void sum_row8(const int4* __restrict__ t,
                                         int st, int en, int sub,
                                         float* __restrict__ acc) {
    const int4* tp = t + sub;
    __half2 z = __float2half2_rn(0.f);
    __half2 a0 = z, a1 = z, a2 = z, a3 = z;
    for (int base = st; base < en; base += 8) {
        int4 cA = __ldg((const int4*)&g_ecol[base]);
        int4 cB = __ldg((const int4*)&g_ecol[base + 4]);
        int4 raw[8];
        raw[0] = __ldg(&tp[(size_t)cA.x * 8]);
        raw[1] = __ldg(&tp[(size_t)cA.y * 8]);
        raw[2] = __ldg(&tp[(size_t)cA.z * 8]);
        raw[3] = __ldg(&tp[(size_t)cA.w * 8]);
        raw[4] = __ldg(&tp[(size_t)cB.x * 8]);
        raw[5] = __ldg(&tp[(size_t)cB.y * 8]);
        raw[6] = __ldg(&tp[(size_t)cB.z * 8]);
        raw[7] = __ldg(&tp[(size_t)cB.w * 8]);
#pragma unroll
        for (int j = 0; j < 8; j++) {
            const __half2* h = (const __half2*)&raw[j];
            a0 = __hadd2(a0, h[0]);
            a1 = __hadd2(a1, h[1]);
            a2 = __hadd2(a2, h[2]);
            a3 = __hadd2(a3, h[3]);
        }
    }
    float2 f0 = __half22float2(a0);
    float2 f1 = __half22float2(a1);
    float2 f2 = __half22float2(a2);
    float2 f3 = __half22float2(a3);
    acc[0] = f0.x; acc[1] = f0.y; acc[2] = f1.x; acc[3] = f1.y;
    acc[4] = f2.x; acc[5] = f2.y; acc[6] = f3.x; acc[7] = f3.y;
}

__device__ __forceinline__ int4 pack8(const float* v) {
    __half2 h0 = __floats2half2_rn(v[0], v[1]);
    __half2 h1 = __floats2half2_rn(v[2], v[3]);
    __half2 h2 = __floats2half2_rn(v[4], v[5]);
    __half2 h3 = __floats2half2_rn(v[6], v[7]);
    int4 r;
    r.x = *(int*)&h0; r.y = *(int*)&h1;
    r.z = *(int*)&h2; r.w = *(int*)&h3;
    return r;
}

__device__ __forceinline__ void unpack8(int4 raw, float* v) {
    const __half2* h = (const __half2*)&raw;
    float2 f0 = __half22float2(h[0]);
    float2 f1 = __half22float2(h[1]);
    float2 f2 = __half22float2(h[2]);
    float2 f3 = __half22float2(h[3]);
    v[0] = f0.x; v[1] = f0.y; v[2] = f1.x; v[3] = f1.y;
    v[4] = f2.x; v[5] = f2.y; v[6] = f3.x; v[7] = f3.y;
}

// k=1: z1 = m1d * sum(z0 over neighbors)
__global__ __launch_bounds__(256) void cheb_first_kernel(const __half* __restrict__ zy,
                                                         __half* __restrict__ zcur) {
    int sub = threadIdx.x & 7;
    int row = blockIdx.x * 32 + (threadIdx.x >> 3);
    if (row >= NN) return;
    int s = row * STRIDE, e = g_cursor[row];
    float acc[8];
    sum_row8((const int4*)zy, s, e, sub, acc);
    float m = g_m1d[row];
    float z1[8];
#pragma unroll
    for (int i = 0; i < 8; i++) z1[i] = m * acc[i];
    ((int4*)zcur)[(size_t)row * 8 + sub] = pack8(z1);
}

// k>=2: zn = 2*m1d*sum(zc) - zp ; out handling (z space):
//   mode 0: none
//   mode 1 (k==2): out  = c0*zp + c1*zc[idx] + c2*zn
//   mode 2 (even): out += c_{k-1}*zc[idx] + c_k*zn
__global__ __launch_bounds__(256) void cheb_step_kernel(const __half* __restrict__ zc,
                                                        const __half* __restrict__ zp,
                                                        __half* __restrict__ zn,
                                                        __half* __restrict__ outb,
                                                        int layer, int k, int mode) {
    int sub = threadIdx.x & 7;
    int row = blockIdx.x * 32 + (threadIdx.x >> 3);
    if (row >= NN) return;
    int s = row * STRIDE, e = g_cursor[row];
    float acc[8];
    sum_row8((const int4*)zc, s, e, sub, acc);
    size_t idx = (size_t)row * 8 + sub;
    float m2 = 2.f * g_m1d[row];
    float p[8], tn[8];
    unpack8(((const int4*)zp)[idx], p);
#pragma unroll
    for (int i = 0; i < 8; i++) tn[i] = m2 * acc[i] - p[i];
    ((int4*)zn)[idx] = pack8(tn);
    if (mode) {
        float ck = g_coeff[layer][k];
        float ckm = g_coeff[layer][k - 1];
        float tc[8], o[8];
        unpack8(((const int4*)zc)[idx], tc);
        if (mode == 1) {
            float c0 = g_coeff[layer][0];
#pragma unroll
            for (int i = 0; i < 8; i++) o[i] = c0 * p[i] + ckm * tc[i] + ck * tn[i];
        } else {
            unpack8(((const int4*)outb)[idx], o);
#pragma unroll
            for (int i = 0; i < 8; i++) o[i] += ckm * tc[i] + ck * tn[i];
        }
        ((int4*)outb)[idx] = pack8(o);
    }
}

// k = KORD-1 (odd): h = relu(rd*(out_z + c_k*zn) + bias)
__global__ __launch_bounds__(256) void cheb_last_kernel(const __half* __restrict__ zc,
                                                        const __half* __restrict__ zp,
                                                        const __half* __restrict__ outb,
                                                        const float* __restrict__ bias,
                                                        __half* __restrict__ hout,
                                                        int layer, int k) {
    int sub = threadIdx.x & 7;
    int row = blockIdx.x * 32 + (threadIdx.x >> 3);
    if (row >= NN) return;
    int s = row * STRIDE, e = g_cursor[row];
    float acc[8];
    sum_row8((const int4*)zc, s, e, sub, acc);
    size_t idx = (size_t)row * 8 + sub;
    float m2 = 2.f * g_m1d[row];
    float rd = g_rd[row];
    float p[8], o[8];
    unpack8(((const int4*)zp)[idx], p);
    unpack8(((const int4*)outb)[idx], o);
    float ck = g_coeff[layer][k];
    float4 b0 = *(const float4*)(bias + sub * 8);
    float4 b1 = *(const float4*)(bias + sub * 8 + 4);
    float bb[8] = {b0.x, b0.y, b0.z, b0.w, b1.x, b1.y, b1.z, b1.w};
    float r[8];
#pragma unroll
    for (int i = 0; i < 8; i++) {
        float tni = m2 * acc[i] - p[i];
        r[i] = fmaxf(rd * (o[i] + ck * tni) + bb[i], 0.f);
    }
    ((int4*)hout)[idx] = pack8(r);
}

// ---------------- pool (fp16 input) + head + log_softmax ----------------
__global__ __launch_bounds__(256) void pool_head_kernel(const __half* __restrict__ h,
                                                        const int* __restrict__ batch,
                                                        const float* __restrict__ lin1w,
                                                        const float* __restrict__ lin1b,
                                                        const float* __restrict__ lin2w,
                                                        const float* __restrict__ lin2b,
                                                        float* __restrict__ out) {
    int g = blockIdx.x;
    int tid = threadIdx.x;
    int lo = 0, hi = NN;
    while (lo < hi) { int m = (lo + hi) >> 1; if (batch[m] < g) lo = m + 1; else hi = m; }
    int start = lo;
    lo = start; hi = NN;
    while (lo < hi) { int m = (lo + hi) >> 1; if (batch[m] < g + 1) lo = m + 1; else hi = m; }
    int end = lo;

    int f = tid & 63, sub = tid >> 6;
    float acc = 0.f;
    for (int i = start + sub; i < end; i += 4)
        acc += __half2float(h[(size_t)i * HID + f]);
    __shared__ float red[4][64];
    red[sub][f] = acc;
    __syncthreads();
    __shared__ float pooled[64];
    if (tid < 64) {
        float s = red[0][tid] + red[1][tid] + red[2][tid] + red[3][tid];
        float cnt = (float)(end - start);
        pooled[tid] = s / fmaxf(cnt, 1.0f);
    }
    __syncthreads();
    __shared__ float g1[64];
    if (tid < 64) {
        float a = lin1b[tid];
        for (int fk = 0; fk < 64; fk++) a += pooled[fk] * lin1w[fk * 64 + tid];
        g1[tid] = fmaxf(a, 0.f);
    }
    __syncthreads();
    __shared__ float logits[NCLS];
    if (tid < NCLS) {
        float a = lin2b[tid];
        for (int fk = 0; fk < 64; fk++) a += g1[fk] * lin2w[fk * NCLS + tid];
        logits[tid] = a;
    }
    __syncthreads();
    __shared__ float s_lse;
    if (tid == 0) {
        float mx = logits[0];
        for (int c = 1; c < NCLS; c++) mx = fmaxf(mx, logits[c]);
        float s = 0.f;
        for (int c = 0; c < NCLS; c++) s += expf(logits[c] - mx);
        s_lse = mx + logf(s);
    }
    __syncthreads();
    if (tid < NCLS) out[g * NCLS + tid] = logits[tid] - s_lse;
}

// ---------------- host orchestration ----------------
static void spectral_layer(const void* hin, int fin, int layer,
                           const float* W, const float* bias,
                           __half* p_yh, __half* p_t1h, __half* p_t2h,
                           __half* p_outh, __half* hout) {
    const int CHEB_GRID = (NN + 31) / 32;
    const int GEMM_GRID = (NN + 127) / 128;
    if (fin == 128)
        gemm_wmma_kernel<128, true><<<GEMM_GRID, 256>>>(hin, W, p_yh);
    else
        gemm_wmma_kernel<64, false><<<GEMM_GRID, 256>>>(hin, W, p_yh);
    cheb_first_kernel<<<CHEB_GRID, 256>>>(p_yh, p_t1h);
    __half* tp = p_yh; __half* tc = p_t1h; __half* tn = p_t2h;
    for (int k = 2; k <= KORD - 2; k++) {
        int mode = (k == 2) ? 1 : ((k & 1) ? 0 : 2);
        cheb_step_kernel<<<CHEB_GRID, 256>>>(tc, tp, tn, p_outh, layer, k, mode);
        __half* tmp = tp; tp = tc; tc = tn; tn = tmp;
    }
    cheb_last_kernel<<<CHEB_GRID, 256>>>(tc, tp, p_outh, bias, hout, layer, KORD - 1);
}

extern "C" void kernel_launch(void* const* d_in, const int* in_sizes, int n_in,
                              void* d_out, int out_size) {
    const float* x      = (const float*)d_in[0];
    const int*   ei     = (const int*)d_in[1];
    const int*   batch  = (const int*)d_in[2];
    const float* W1     = (const float*)d_in[3];
    const float* theta1 = (const float*)d_in[4];
    const float* b1     = (const float*)d_in[5];
    const float* Ws     = (const float*)d_in[6];
    const float* thetas = (const float*)d_in[7];
    const float* bs     = (const float*)d_in[8];
    const float* lin1w  = (const float*)d_in[9];
    const float* lin1b  = (const float*)d_in[10];
    const float* lin2w  = (const float*)d_in[11];
    const float* lin2b  = (const float*)d_in[12];
    float* out = (float*)d_out;

    const int* row = ei;
    const int* col = ei + EE;

    void* pv;
    __half *p_yh, *p_t1h, *p_t2h, *p_outh, *p_hh;
    cudaGetSymbolAddress(&pv, g_yh);   p_yh  = (__half*)pv;
    cudaGetSymbolAddress(&pv, g_t1h);  p_t1h = (__half*)pv;
    cudaGetSymbolAddress(&pv, g_t2h);  p_t2h = (__half*)pv;
    cudaGetSymbolAddress(&pv, g_outh); p_outh = (__half*)pv;
    cudaGetSymbolAddress(&pv, g_hh);   p_hh  = (__half*)pv;

    // ---- one-pass fixed-stride CSR build (cols only) ----
    init_kernel<<<(NN + 255) / 256, 256>>>();
    scatter_kernel<<<(EE / 4 + 255) / 256, 256>>>(row, col);
    dinv_coeff_pad_kernel<<<(NN + 255) / 256, 256>>>(theta1, thetas);

    // ---- 3 spectral layers ----
    spectral_layer(x,    128, 0, W1,           b1,       p_yh, p_t1h, p_t2h, p_outh, p_hh);
    spectral_layer(p_hh,  64, 1, Ws,           bs,       p_yh, p_t1h, p_t2h, p_outh, p_hh);
    spectral_layer(p_hh,  64, 2, Ws + 64 * 64, bs + HID, p_yh, p_t1h, p_t2h, p_outh, p_hh);

    // ---- pool + head ----
    pool_head_kernel<<<NGRAPH, 256>>>(p_hh, batch, lin1w, lin1b, lin2w, lin2b, out);
}

// round 17
// speedup vs baseline: 1.8650x; 1.0830x over previous
#include <cuda_runtime.h>
#include <cuda_fp16.h>
#include <mma.h>
#include <math.h>

using namespace nvcuda;

#define NN 100000
#define EE 1600000
#define STRIDE 96                      // fixed edge slots per row (max deg ~50 << 96)
#define HID 64
#define KORD 14
#define HEADS 8
#define NGRAPH 128
#define NCLS 10

// ---------------- scratch (device globals; no runtime alloc) ----------------
// z-space Chebyshev buffers have an extra zero row (index NN) for padding edges.
__device__ __half g_yh  [(NN + 1) * HID];
__device__ __half g_t1h [(NN + 1) * HID];
__device__ __half g_t2h [(NN + 1) * HID];
__device__ __half g_outh[NN * HID];
__device__ __half g_hh  [NN * HID];
__device__ float  g_dinv[NN];          // dinv_i = rsqrt(max(deg,1))
__device__ float  g_m1d [NN];          // -dinv_i^2
__device__ float  g_rd  [NN];          // 1/dinv_i
__device__ int    g_cursor[NN];        // scatter cursor; after pad: padded row end
__device__ int    g_ecol[NN * STRIDE]; // column indices (padding -> NN)
__device__ float  g_coeff[3][KORD];

// ---------------- init: cursor = row base; zero dummy row of z buffers ----------------
__global__ void init_kernel() {
    int i = blockIdx.x * blockDim.x + threadIdx.x;
    if (i < NN) g_cursor[i] = i * STRIDE;
    if (i < 8 * 3) {
        int b = i >> 3, j = i & 7;
        __half* buf = (b == 0) ? g_yh : (b == 1) ? g_t1h : g_t2h;
        ((int4*)buf)[(size_t)NN * 8 + j] = make_int4(0, 0, 0, 0);
    }
}

// one-pass scatter: columns only, 4 edges per thread
__global__ void scatter_kernel(const int* __restrict__ row, const int* __restrict__ col) {
    int e = (blockIdx.x * blockDim.x + threadIdx.x) * 4;
    if (e < EE) {
        int4 rr = *(const int4*)(row + e);
        int4 cc = *(const int4*)(col + e);
        int pos;
        pos = atomicAdd(&g_cursor[rr.x], 1); g_ecol[pos] = cc.x;
        pos = atomicAdd(&g_cursor[rr.y], 1); g_ecol[pos] = cc.y;
        pos = atomicAdd(&g_cursor[rr.z], 1); g_ecol[pos] = cc.z;
        pos = atomicAdd(&g_cursor[rr.w], 1); g_ecol[pos] = cc.w;
    }
}

// dinv/m1d/rd from cursor delta + per-layer coeff (block 0) + pad cols with NN (mult of 4)
__global__ void dinv_coeff_pad_kernel(const float* __restrict__ theta1,
                                      const float* __restrict__ thetas) {
    int i = blockIdx.x * blockDim.x + threadIdx.x;
    if (i < NN) {
        int base = i * STRIDE;
        int deg = g_cursor[i] - base;
        float df = fmaxf((float)deg, 1.0f);
        float dv = rsqrtf(df);
        g_dinv[i] = dv;
        g_m1d[i] = -dv * dv;
        g_rd[i] = sqrtf(df);
        int pend = (deg + 3) & ~3;
        for (int j = deg; j < pend; j++) g_ecol[base + j] = NN;   // dummy zero row
        g_cursor[i] = base + pend;
    }
    if (blockIdx.x == 0 && threadIdx.x < 3 * KORD) {
        int layer = threadIdx.x / KORD, k = threadIdx.x % KORD;
        const float* th = (layer == 0) ? theta1 : thetas + (layer - 1) * HEADS * KORD;
        float s = 0.f;
        for (int h = 0; h < HEADS; h++) s += th[h * KORD + k];
        g_coeff[layer][k] = s * (1.0f / HEADS);
    }
}

// ---------------- wmma GEMM: Zh[N][64] = dinv * (A[N][FIN] @ W[FIN][64]) ----------------
// Software-pipelined: next K-chunk prefetched into registers while current
// chunk is consumed from smem (overlaps DRAM latency with MMA).
template <int FIN, bool A_IS_FLOAT>
__global__ __launch_bounds__(256) void gemm_wmma_kernel(const void* __restrict__ Ain,
                                                        const float* __restrict__ W,
                                                        __half* __restrict__ Zh) {
    __shared__ __half As[128][40];
    __shared__ __half Ws[32][72];
    __shared__ float  Wb[8][16 * 20];
    constexpr int NCHUNK = FIN / 32;
    int rowbase = blockIdx.x * 128;
    int tid = threadIdx.x;
    int wid = tid >> 5;
    int lane = tid & 31;

    wmma::fragment<wmma::accumulator, 16, 16, 16, float> acc[4];
#pragma unroll
    for (int i = 0; i < 4; i++) wmma::fill_fragment(acc[i], 0.f);

    int2  aPk[4];       // prefetched A (already fp16-packed)
    int2  wPk[2];       // prefetched W (fp16-packed)

    auto prefetch = [&](int kk) {
#pragma unroll
        for (int i = 0; i < 4; i++) {
            int j = tid * 4 + i;
            int r = j >> 3;
            int kq = j & 7;
            int gr = rowbase + r;
            int2 pk = make_int2(0, 0);
            if (gr < NN) {
                if (A_IS_FLOAT) {
                    float4 v = *(const float4*)((const float*)Ain + (size_t)gr * FIN + kk + kq * 4);
                    __half2 h0 = __floats2half2_rn(v.x, v.y);
                    __half2 h1 = __floats2half2_rn(v.z, v.w);
                    pk.x = *(int*)&h0; pk.y = *(int*)&h1;
                } else {
                    pk = *(const int2*)((const __half*)Ain + (size_t)gr * FIN + kk + kq * 4);
                }
            }
            aPk[i] = pk;
        }
#pragma unroll
        for (int i = 0; i < 2; i++) {
            int j = tid * 2 + i;
            int k = j >> 4;
            int nq = j & 15;
            float4 v = *(const float4*)(W + (size_t)(kk + k) * 64 + nq * 4);
            __half2 h0 = __floats2half2_rn(v.x, v.y);
            __half2 h1 = __floats2half2_rn(v.z, v.w);
            wPk[i].x = *(int*)&h0; wPk[i].y = *(int*)&h1;
        }
    };

    prefetch(0);
#pragma unroll
    for (int c = 0; c < NCHUNK; c++) {
#pragma unroll
        for (int i = 0; i < 4; i++) {
            int j = tid * 4 + i;
            int r = j >> 3;
            int kq = j & 7;
            *(int2*)&As[r][kq * 4] = aPk[i];
        }
#pragma unroll
        for (int i = 0; i < 2; i++) {
            int j = tid * 2 + i;
            int k = j >> 4;
            int nq = j & 15;
            *(int2*)&Ws[k][nq * 4] = wPk[i];
        }
        __syncthreads();
        if (c + 1 < NCHUNK) prefetch((c + 1) * 32);
#pragma unroll
        for (int ks = 0; ks < 32; ks += 16) {
            wmma::fragment<wmma::matrix_a, 16, 16, 16, __half, wmma::row_major> a_frag;
            wmma::load_matrix_sync(a_frag, &As[wid * 16][ks], 40);
#pragma unroll
            for (int nb = 0; nb < 4; nb++) {
                wmma::fragment<wmma::matrix_b, 16, 16, 16, __half, wmma::row_major> b_frag;
                wmma::load_matrix_sync(b_frag, &Ws[ks][nb * 16], 72);
                wmma::mma_sync(acc[nb], a_frag, b_frag, acc[nb]);
            }
        }
        __syncthreads();
    }
    // epilogue: scale by dinv (y -> z space), pack fp16
#pragma unroll
    for (int nb = 0; nb < 4; nb++) {
        wmma::store_matrix_sync(&Wb[wid][0], acc[nb], 20, wmma::mem_row_major);
        __syncwarp();
        int r = lane >> 1;
        int hc = lane & 1;
        int gr = rowbase + wid * 16 + r;
        if (gr < NN) {
            float dv = g_dinv[gr];
            const float* src = &Wb[wid][r * 20 + hc * 8];
            __half2 o0 = __floats2half2_rn(dv * src[0], dv * src[1]);
            __half2 o1 = __floats2half2_rn(dv * src[2], dv * src[3]);
            __half2 o2 = __floats2half2_rn(dv * src[4], dv * src[5]);
            __half2 o3 = __floats2half2_rn(dv * src[6], dv * src[7]);
            int4 pk;
            pk.x = *(int*)&o0; pk.y = *(int*)&o1;
            pk.z = *(int*)&o2; pk.w = *(int*)&o3;
            *(int4*)(Zh + (size_t)gr * 64 + nb * 16 + hc * 8) = pk;
        }
        __syncwarp();
    }
}

// ---------------- unweighted neighbor sum: 8-lane group per row, 8 features/lane ----------------
// 4-edge chunks (CSR padded to multiples of 4): one broadcast int4 col load,
// 4 front-batched 16B gathers, fp16 __hadd2 accumulation.
__device__ __forceinline__ void sum_row8(const int4* __restrict__ t,
                                         int st, int en, int sub,
                                         float* __restrict__ acc) {
    const int4* tp = t + sub;
    __half2 z = __float2half2_rn(0.f);
    __half2 a0 = z, a1 = z, a2 = z, a3 = z;
    for (int base = st; base < en; base += 4) {
        // all 8 lanes of the group load the same 16B of columns -> L1 broadcast
        int4 c = __ldg((const int4*)&g_ecol[base]);
        int4 r0 = __ldg(&tp[(size_t)c.x * 8]);
        int4 r1 = __ldg(&tp[(size_t)c.y * 8]);
        int4 r2 = __ldg(&tp[(size_t)c.z * 8]);
        int4 r3 = __ldg(&tp[(size_t)c.w * 8]);
        const __half2* h0 = (const __half2*)&r0;
        const __half2* h1 = (const __half2*)&r1;
        const __half2* h2 = (const __half2*)&r2;
        const __half2* h3 = (const __half2*)&r3;
        a0 = __hadd2(__hadd2(a0, h0[0]), __hadd2(h1[0], __hadd2(h2[0], h3[0])));
        a1 = __hadd2(__hadd2(a1, h0[1]), __hadd2(h1[1], __hadd2(h2[1], h3[1])));
        a2 = __hadd2(__hadd2(a2, h0[2]), __hadd2(h1[2], __hadd2(h2[2], h3[2])));
        a3 = __hadd2(__hadd2(a3, h0[3]), __hadd2(h1[3], __hadd2(h2[3], h3[3])));
    }
    float2 f0 = __half22float2(a0);
    float2 f1 = __half22float2(a1);
    float2 f2 = __half22float2(a2);
    float2 f3 = __half22float2(a3);
    acc[0] = f0.x; acc[1] = f0.y; acc[2] = f1.x; acc[3] = f1.y;
    acc[4] = f2.x; acc[5] = f2.y; acc[6] = f3.x; acc[7] = f3.y;
}

__device__ __forceinline__ int4 pack8(const float* v) {
    __half2 h0 = __floats2half2_rn(v[0], v[1]);
    __half2 h1 = __floats2half2_rn(v[2], v[3]);
    __half2 h2 = __floats2half2_rn(v[4], v[5]);
    __half2 h3 = __floats2half2_rn(v[6], v[7]);
    int4 r;
    r.x = *(int*)&h0; r.y = *(int*)&h1;
    r.z = *(int*)&h2; r.w = *(int*)&h3;
    return r;
}

__device__ __forceinline__ void unpack8(int4 raw, float* v) {
    const __half2* h = (const __half2*)&raw;
    float2 f0 = __half22float2(h[0]);
    float2 f1 = __half22float2(h[1]);
    float2 f2 = __half22float2(h[2]);
    float2 f3 = __half22float2(h[3]);
    v[0] = f0.x; v[1] = f0.y; v[2] = f1.x; v[3] = f1.y;
    v[4] = f2.x; v[5] = f2.y; v[6] = f3.x; v[7] = f3.y;
}

// k=1: z1 = m1d * sum(z0 over neighbors)
__global__ __launch_bounds__(256) void cheb_first_kernel(const __half* __restrict__ zy,
                                                         __half* __restrict__ zcur) {
    int sub = threadIdx.x & 7;
    int row = blockIdx.x * 32 + (threadIdx.x >> 3);
    if (row >= NN) return;
    int s = row * STRIDE, e = g_cursor[row];
    float acc[8];
    sum_row8((const int4*)zy, s, e, sub, acc);
    float m = g_m1d[row];
    float z1[8];
#pragma unroll
    for (int i = 0; i < 8; i++) z1[i] = m * acc[i];
    ((int4*)zcur)[(size_t)row * 8 + sub] = pack8(z1);
}

// k>=2: zn = 2*m1d*sum(zc) - zp ; out handling (z space):
//   mode 0: none
//   mode 1 (k==2): out  = c0*zp + c1*zc[idx] + c2*zn
//   mode 2 (even): out += c_{k-1}*zc[idx] + c_k*zn
__global__ __launch_bounds__(256) void cheb_step_kernel(const __half* __restrict__ zc,
                                                        const __half* __restrict__ zp,
                                                        __half* __restrict__ zn,
                                                        __half* __restrict__ outb,
                                                        int layer, int k, int mode) {
    int sub = threadIdx.x & 7;
    int row = blockIdx.x * 32 + (threadIdx.x >> 3);
    if (row >= NN) return;
    int s = row * STRIDE, e = g_cursor[row];
    float acc[8];
    sum_row8((const int4*)zc, s, e, sub, acc);
    size_t idx = (size_t)row * 8 + sub;
    float m2 = 2.f * g_m1d[row];
    float p[8], tn[8];
    unpack8(((const int4*)zp)[idx], p);
#pragma unroll
    for (int i = 0; i < 8; i++) tn[i] = m2 * acc[i] - p[i];
    ((int4*)zn)[idx] = pack8(tn);
    if (mode) {
        float ck = g_coeff[layer][k];
        float ckm = g_coeff[layer][k - 1];
        float tc[8], o[8];
        unpack8(((const int4*)zc)[idx], tc);
        if (mode == 1) {
            float c0 = g_coeff[layer][0];
#pragma unroll
            for (int i = 0; i < 8; i++) o[i] = c0 * p[i] + ckm * tc[i] + ck * tn[i];
        } else {
            unpack8(((const int4*)outb)[idx], o);
#pragma unroll
            for (int i = 0; i < 8; i++) o[i] += ckm * tc[i] + ck * tn[i];
        }
        ((int4*)outb)[idx] = pack8(o);
    }
}

// k = KORD-1 (odd): h = relu(rd*(out_z + c_k*zn) + bias)
__global__ __launch_bounds__(256) void cheb_last_kernel(const __half* __restrict__ zc,
                                                        const __half* __restrict__ zp,
                                                        const __half* __restrict__ outb,
                                                        const float* __restrict__ bias,
                                                        __half* __restrict__ hout,
                                                        int layer, int k) {
    int sub = threadIdx.x & 7;
    int row = blockIdx.x * 32 + (threadIdx.x >> 3);
    if (row >= NN) return;
    int s = row * STRIDE, e = g_cursor[row];
    float acc[8];
    sum_row8((const int4*)zc, s, e, sub, acc);
    size_t idx = (size_t)row * 8 + sub;
    float m2 = 2.f * g_m1d[row];
    float rd = g_rd[row];
    float p[8], o[8];
    unpack8(((const int4*)zp)[idx], p);
    unpack8(((const int4*)outb)[idx], o);
    float ck = g_coeff[layer][k];
    float4 b0 = *(const float4*)(bias + sub * 8);
    float4 b1 = *(const float4*)(bias + sub * 8 + 4);
    float bb[8] = {b0.x, b0.y, b0.z, b0.w, b1.x, b1.y, b1.z, b1.w};
    float r[8];
#pragma unroll
    for (int i = 0; i < 8; i++) {
        float tni = m2 * acc[i] - p[i];
        r[i] = fmaxf(rd * (o[i] + ck * tni) + bb[i], 0.f);
    }
    ((int4*)hout)[idx] = pack8(r);
}

// ---------------- pool (fp16 input) + head + log_softmax ----------------
__global__ __launch_bounds__(256) void pool_head_kernel(const __half* __restrict__ h,
                                                        const int* __restrict__ batch,
                                                        const float* __restrict__ lin1w,
                                                        const float* __restrict__ lin1b,
                                                        const float* __restrict__ lin2w,
                                                        const float* __restrict__ lin2b,
                                                        float* __restrict__ out) {
    int g = blockIdx.x;
    int tid = threadIdx.x;
    int lo = 0, hi = NN;
    while (lo < hi) { int m = (lo + hi) >> 1; if (batch[m] < g) lo = m + 1; else hi = m; }
    int start = lo;
    lo = start; hi = NN;
    while (lo < hi) { int m = (lo + hi) >> 1; if (batch[m] < g + 1) lo = m + 1; else hi = m; }
    int end = lo;

    int f = tid & 63, sub = tid >> 6;
    float acc = 0.f;
    for (int i = start + sub; i < end; i += 4)
        acc += __half2float(h[(size_t)i * HID + f]);
    __shared__ float red[4][64];
    red[sub][f] = acc;
    __syncthreads();
    __shared__ float pooled[64];
    if (tid < 64) {
        float s = red[0][tid] + red[1][tid] + red[2][tid] + red[3][tid];
        float cnt = (float)(end - start);
        pooled[tid] = s / fmaxf(cnt, 1.0f);
    }
    __syncthreads();
    __shared__ float g1[64];
    if (tid < 64) {
        float a = lin1b[tid];
        for (int fk = 0; fk < 64; fk++) a += pooled[fk] * lin1w[fk * 64 + tid];
        g1[tid] = fmaxf(a, 0.f);
    }
    __syncthreads();
    __shared__ float logits[NCLS];
    if (tid < NCLS) {
        float a = lin2b[tid];
        for (int fk = 0; fk < 64; fk++) a += g1[fk] * lin2w[fk * NCLS + tid];
        logits[tid] = a;
    }
    __syncthreads();
    __shared__ float s_lse;
    if (tid == 0) {
        float mx = logits[0];
        for (int c = 1; c < NCLS; c++) mx = fmaxf(mx, logits[c]);
        float s = 0.f;
        for (int c = 0; c < NCLS; c++) s += expf(logits[c] - mx);
        s_lse = mx + logf(s);
    }
    __syncthreads();
    if (tid < NCLS) out[g * NCLS + tid] = logits[tid] - s_lse;
}

// ---------------- host orchestration ----------------
static void spectral_layer(const void* hin, int fin, int layer,
                           const float* W, const float* bias,
                           __half* p_yh, __half* p_t1h, __half* p_t2h,
                           __half* p_outh, __half* hout) {
    const int CHEB_GRID = (NN + 31) / 32;
    const int GEMM_GRID = (NN + 127) / 128;
    if (fin == 128)
        gemm_wmma_kernel<128, true><<<GEMM_GRID, 256>>>(hin, W, p_yh);
    else
        gemm_wmma_kernel<64, false><<<GEMM_GRID, 256>>>(hin, W, p_yh);
    cheb_first_kernel<<<CHEB_GRID, 256>>>(p_yh, p_t1h);
    __half* tp = p_yh; __half* tc = p_t1h; __half* tn = p_t2h;
    for (int k = 2; k <= KORD - 2; k++) {
        int mode = (k == 2) ? 1 : ((k & 1) ? 0 : 2);
        cheb_step_kernel<<<CHEB_GRID, 256>>>(tc, tp, tn, p_outh, layer, k, mode);
        __half* tmp = tp; tp = tc; tc = tn; tn = tmp;
    }
    cheb_last_kernel<<<CHEB_GRID, 256>>>(tc, tp, p_outh, bias, hout, layer, KORD - 1);
}

extern "C" void kernel_launch(void* const* d_in, const int* in_sizes, int n_in,
                              void* d_out, int out_size) {
    const float* x      = (const float*)d_in[0];
    const int*   ei     = (const int*)d_in[1];
    const int*   batch  = (const int*)d_in[2];
    const float* W1     = (const float*)d_in[3];
    const float* theta1 = (const float*)d_in[4];
    const float* b1     = (const float*)d_in[5];
    const float* Ws     = (const float*)d_in[6];
    const float* thetas = (const float*)d_in[7];
    const float* bs     = (const float*)d_in[8];
    const float* lin1w  = (const float*)d_in[9];
    const float* lin1b  = (const float*)d_in[10];
    const float* lin2w  = (const float*)d_in[11];
    const float* lin2b  = (const float*)d_in[12];
    float* out = (float*)d_out;

    const int* row = ei;
    const int* col = ei + EE;

    void* pv;
    __half *p_yh, *p_t1h, *p_t2h, *p_outh, *p_hh;
    cudaGetSymbolAddress(&pv, g_yh);   p_yh  = (__half*)pv;
    cudaGetSymbolAddress(&pv, g_t1h);  p_t1h = (__half*)pv;
    cudaGetSymbolAddress(&pv, g_t2h);  p_t2h = (__half*)pv;
    cudaGetSymbolAddress(&pv, g_outh); p_outh = (__half*)pv;
    cudaGetSymbolAddress(&pv, g_hh);   p_hh  = (__half*)pv;

    // ---- one-pass fixed-stride CSR build (cols only) ----
    init_kernel<<<(NN + 255) / 256, 256>>>();
    scatter_kernel<<<(EE / 4 + 255) / 256, 256>>>(row, col);
    dinv_coeff_pad_kernel<<<(NN + 255) / 256, 256>>>(theta1, thetas);

    // ---- 3 spectral layers ----
    spectral_layer(x,    128, 0, W1,           b1,       p_yh, p_t1h, p_t2h, p_outh, p_hh);
    spectral_layer(p_hh,  64, 1, Ws,           bs,       p_yh, p_t1h, p_t2h, p_outh, p_hh);
    spectral_layer(p_hh,  64, 2, Ws + 64 * 64, bs + HID, p_yh, p_t1h, p_t2h, p_outh, p_hh);

    // ---- pool + head ----
    pool_head_kernel<<<NGRAPH, 256>>>(p_hh, batch, lin1w, lin1b, lin2w, lin2b, out);
}